// round 10
// baseline (speedup 1.0000x reference)
#include <cuda_runtime.h>
#include <cuda_fp16.h>
#include <cstdint>

// Shapes: Q[2,2048,1024], mask[2,2048], W_*[1024,1024], b_*[1024], out[2,2048,1024] fp32
// Scratch (fp16): g_qh,g_kh [bh][s][64]; g_vTh [bh][64(dv)][2048(s)];
//                 g_Ah = fp16 Q-input, g_Wh = fp16 weights
__device__ __align__(16) __half g_qh [2 * 16 * 2048 * 64];
__device__ __align__(16) __half g_kh [2 * 16 * 2048 * 64];
__device__ __align__(16) __half g_vTh[2 * 16 * 64 * 2048];
__device__ __align__(16) __half g_Ah [4096 * 1024];
__device__ __align__(16) __half g_Wh [3][1024 * 1024];

// ---------------------------------------------------------------------------
// helpers
// ---------------------------------------------------------------------------
__device__ __forceinline__ uint32_t packh(float lo, float hi) {
    uint32_t d;
    asm("cvt.rn.f16x2.f32 %0, %1, %2;" : "=r"(d) : "f"(hi), "f"(lo));
    return d;
}
__device__ __forceinline__ uint32_t smem_u32(const void* p) {
    uint32_t a;
    asm("{ .reg .u64 t; cvta.to.shared.u64 t, %1; cvt.u32.u64 %0, t; }" : "=r"(a) : "l"(p));
    return a;
}
__device__ __forceinline__ void ldsm4(uint32_t* r, uint32_t addr) {
    asm volatile("ldmatrix.sync.aligned.m8n8.x4.shared.b16 {%0,%1,%2,%3}, [%4];"
                 : "=r"(r[0]), "=r"(r[1]), "=r"(r[2]), "=r"(r[3]) : "r"(addr));
}
__device__ __forceinline__ void mma16(float* c, const uint32_t* a, const uint32_t* b) {
    asm volatile(
        "mma.sync.aligned.m16n8k16.row.col.f32.f16.f16.f32 "
        "{%0,%1,%2,%3}, {%4,%5,%6,%7}, {%8,%9}, {%0,%1,%2,%3};"
        : "+f"(c[0]), "+f"(c[1]), "+f"(c[2]), "+f"(c[3])
        : "r"(a[0]), "r"(a[1]), "r"(a[2]), "r"(a[3]), "r"(b[0]), "r"(b[1]));
}
__device__ __forceinline__ void cpa16(uint32_t dst, const void* src) {
    asm volatile("cp.async.ca.shared.global [%0], [%1], 16;" :: "r"(dst), "l"(src));
}
#define CP_COMMIT() asm volatile("cp.async.commit_group;" ::: "memory")
#define CP_WAIT1()  asm volatile("cp.async.wait_group 1;" ::: "memory")

// A-operand ldmatrix byte address (16-row x k16 tile)
__device__ __forceinline__ uint32_t a_addr_h(const __half* base, int rowBase, int stride, int lane) {
    const int row = rowBase + ((lane >> 3) & 1) * 8 + (lane & 7);
    const int col = (lane >> 4) << 3;
    return smem_u32(base + row * stride + col);
}
// B-pair ldmatrix byte address -> {r0,r1}=n-group0, {r2,r3}=n-group1
__device__ __forceinline__ uint32_t b_addr_h(const __half* base, int rowBase, int stride, int lane) {
    const int sel = lane >> 3;
    const int row = rowBase + (sel >> 1) * 8 + (lane & 7);
    const int col = (sel & 1) << 3;
    return smem_u32(base + row * stride + col);
}

// ---------------------------------------------------------------------------
// fp16 pre-convert
// ---------------------------------------------------------------------------
__global__ __launch_bounds__(256)
void round_kernel(const float* __restrict__ Qin,
                  const float* __restrict__ Wq,
                  const float* __restrict__ Wk,
                  const float* __restrict__ Wv)
{
    const int i = blockIdx.x * 256 + threadIdx.x;
    const int y = blockIdx.y;
    const float* src;
    __half* dst;
    if (y == 0) { src = Qin; dst = g_Ah; }
    else        { if (i >= 262144) return;
                  src = (y == 1) ? Wq : (y == 2) ? Wk : Wv; dst = g_Wh[y - 1]; }
    const float4 v = ((const float4*)src)[i];
    ((uint2*)dst)[i] = make_uint2(packh(v.x, v.y), packh(v.z, v.w));
}

// ---------------------------------------------------------------------------
// Projection GEMM (fp16 mma): tile M=128 N=128, K-chunk 64 (4 k16 steps),
// cp.async 2-stage, 16 mainloop iterations. 256 thr. grid = (8, 32, 3).
// ---------------------------------------------------------------------------
#define PSTR 72
#define PSTG_B (256 * PSTR * 2)

__global__ __launch_bounds__(256, 2)
void proj_kernel(const float* __restrict__ bq,
                 const float* __restrict__ bk,
                 const float* __restrict__ bv)
{
    __shared__ __align__(16) __half sbuf[2][256 * PSTR];
    __shared__ float s_bias[128];

    const int proj = blockIdx.z;
    const __half* A = g_Ah;
    const __half* W = g_Wh[proj];
    const float* bias = (proj == 0) ? bq : (proj == 1) ? bk : bv;

    const int tid  = threadIdx.x;
    const int lane = tid & 31;
    const int w    = tid >> 5;
    const int g    = lane >> 2;
    const int cq   = lane & 3;
    const int mw   = (w & 3) << 5;
    const int nw   = (w >> 2) << 6;
    const int m0   = blockIdx.y << 7;
    const int n0   = blockIdx.x << 7;

    if (tid < 128) s_bias[tid] = bias[n0 + tid];

    const uint32_t uS = smem_u32(sbuf);

    const uint32_t aAdr0 = a_addr_h(&sbuf[0][0], mw,      PSTR, lane);
    const uint32_t aAdr1 = a_addr_h(&sbuf[0][0], mw + 16, PSTR, lane);
    uint32_t bAdr[4];
    #pragma unroll
    for (int j = 0; j < 4; j++)
        bAdr[j] = b_addr_h(&sbuf[0][128 * PSTR], nw + 16 * j, PSTR, lane);

    const __half* srcbase = (tid < 128) ? (A + (size_t)(m0 + tid) * 1024)
                                        : (W + (size_t)(n0 + tid - 128) * 1024);
    const uint32_t drow = uS + (uint32_t)(tid * PSTR) * 2;

    float acc[2][8][4] = {};

    #pragma unroll
    for (int st = 0; st < 2; st++) {
        const int k0 = st << 6;
        #pragma unroll
        for (int i = 0; i < 8; i++)
            cpa16(drow + st * PSTG_B + i * 16, srcbase + k0 + i * 8);
        CP_COMMIT();
    }

    for (int c = 0; c < 16; ++c) {
        const int st = c & 1;
        const uint32_t stoff = (uint32_t)st * PSTG_B;
        CP_WAIT1();
        __syncthreads();

        #pragma unroll
        for (int ks = 0; ks < 4; ++ks) {
            const uint32_t koff = stoff + (uint32_t)(ks << 5);
            uint32_t a0[4], a1[4];
            ldsm4(a0, aAdr0 + koff);
            ldsm4(a1, aAdr1 + koff);
            #pragma unroll
            for (int j = 0; j < 4; j++) {
                uint32_t bb[4];
                ldsm4(bb, bAdr[j] + koff);
                mma16(acc[0][2 * j],     a0, bb);
                mma16(acc[0][2 * j + 1], a0, bb + 2);
                mma16(acc[1][2 * j],     a1, bb);
                mma16(acc[1][2 * j + 1], a1, bb + 2);
            }
        }
        __syncthreads();

        if (c + 2 < 16) {
            const int k0 = (c + 2) << 6;
            #pragma unroll
            for (int i = 0; i < 8; i++)
                cpa16(drow + stoff + i * 16, srcbase + k0 + i * 8);
        }
        CP_COMMIT();
    }

    const int h = (n0 + nw) >> 6;
    #pragma unroll
    for (int mt = 0; mt < 2; mt++) {
        const int m  = m0 + mw + (mt << 4) + g;
        const int b_ = m >> 11;
        const int s  = m & 2047;
        const int bh = b_ * 16 + h;
        #pragma unroll
        for (int nt = 0; nt < 8; nt++) {
            const int col  = nw + (nt << 3) + (cq << 1);
            const int colh = col & 63;
            const float b0 = s_bias[col], b1 = s_bias[col + 1];
            if (proj < 2) {
                __half* dst = (proj == 0) ? g_qh : g_kh;
                *(uint32_t*)&dst[(size_t)(bh * 2048 + s) * 64 + colh] =
                    packh(acc[mt][nt][0] + b0, acc[mt][nt][1] + b1);
                *(uint32_t*)&dst[(size_t)(bh * 2048 + s + 8) * 64 + colh] =
                    packh(acc[mt][nt][2] + b0, acc[mt][nt][3] + b1);
            } else {
                g_vTh[(size_t)(bh * 64 + colh)     * 2048 + s]     = __float2half_rn(acc[mt][nt][0] + b0);
                g_vTh[(size_t)(bh * 64 + colh + 1) * 2048 + s]     = __float2half_rn(acc[mt][nt][1] + b1);
                g_vTh[(size_t)(bh * 64 + colh)     * 2048 + s + 8] = __float2half_rn(acc[mt][nt][2] + b0);
                g_vTh[(size_t)(bh * 64 + colh + 1) * 2048 + s + 8] = __float2half_rn(acc[mt][nt][3] + b1);
            }
        }
    }
}

// ---------------------------------------------------------------------------
// Attention v8 (fp16): R8 config (128 thr, 2 blocks/SM, Q-frag reg cache) +
// 128-key pipeline stages (two 64-key halves per stage -> half the barriers).
// K stage: [128 key][72]; V stage: [64 dv][136]; mask stage: [128] f32.
// ---------------------------------------------------------------------------
#define HSTR 72
#define VSTR 136
#define KSTG_B (128 * HSTR * 2)        // 18432
#define VSTG_B (64 * VSTR * 2)         // 17408
#define ATTN_SMEM_BYTES (128 * HSTR * 2 + 2 * KSTG_B + 2 * VSTG_B + 2 * 128 * 4)

__global__ __launch_bounds__(128, 2)
void attn_kernel(const float* __restrict__ mask, float* __restrict__ out)
{
    extern __shared__ __align__(16) __half smh[];
    __half* Qs = smh;                          // [128 q][72]
    __half* Ks = smh + 128 * HSTR;             // [2][128 key][72]
    __half* Vs = Ks + 2 * 128 * HSTR;          // [2][64 dv][136]
    float* maskS = (float*)(Vs + 2 * 64 * VSTR);   // [2][128]

    const int tid  = threadIdx.x;
    const int lane = tid & 31;
    const int w    = tid >> 5;
    const int g    = lane >> 2;
    const int cq   = lane & 3;
    const int qw   = w << 5;
    const int q0   = blockIdx.x << 7;
    const int bh   = blockIdx.y;
    const int b    = bh >> 4;
    const int h    = bh & 15;

    const uint32_t uQ = smem_u32(Qs);
    const uint32_t uK = smem_u32(Ks);
    const uint32_t uV = smem_u32(Vs);
    const uint32_t uM = smem_u32(maskS);

    uint32_t kAdr[4], vAdr[4];
    #pragma unroll
    for (int j = 0; j < 4; j++) {
        kAdr[j] = b_addr_h(Ks, 16 * j, HSTR, lane);   // key-group rows (dk cols)
        vAdr[j] = b_addr_h(Vs, 16 * j, VSTR, lane);   // dv-group rows (key cols)
    }

    const int r2  = tid >> 1;              // 0..63
    const int sBv = (tid & 1) * 128;       // V: byte offset within 256B row

    // ---- preload: Q (128 rows) + stages 0,1 (keys 0-127, 128-255) + mask ----
    #pragma unroll
    for (int i = 0; i < 8; i++)
        cpa16(uQ + (uint32_t)(tid * HSTR) * 2 + i * 16,
              g_qh + (size_t)(bh * 2048 + q0 + tid) * 64 + i * 8);
    #pragma unroll
    for (int st = 0; st < 2; st++) {
        const int kb = st << 7;
        #pragma unroll
        for (int i = 0; i < 8; i++)      // K: thread = one key row, 128B
            cpa16(uK + st * KSTG_B + (uint32_t)(tid * HSTR) * 2 + i * 16,
                  g_kh + (size_t)(bh * 2048 + kb + tid) * 64 + i * 8);
        #pragma unroll
        for (int i = 0; i < 8; i++)      // V: 2 threads per dv row, 256B/row
            cpa16(uV + st * VSTG_B + (uint32_t)(r2 * VSTR) * 2 + sBv + i * 16,
                  g_vTh + (size_t)(bh * 64 + r2) * 2048 + kb + (sBv >> 1) + i * 8);
        if (tid < 32) cpa16(uM + st * 512 + tid * 16, mask + b * 2048 + kb + tid * 4);
        CP_COMMIT();
    }
    CP_WAIT1();
    __syncthreads();

    // ---- Q fragments: load once, keep in regs ----
    uint32_t qa[2][4][4];
    #pragma unroll
    for (int mt = 0; mt < 2; mt++) {
        const uint32_t qb = a_addr_h(Qs, qw + (mt << 4), HSTR, lane);
        #pragma unroll
        for (int ks = 0; ks < 4; ks++)
            ldsm4(qa[mt][ks], qb + (ks << 5));
    }

    float acc[16][4] = {};
    float rs[4] = {};

    for (int st = 0; st < 16; st++) {
        const int cur = st & 1;
        const uint32_t kbase = (uint32_t)cur * KSTG_B;
        const uint32_t vbase = (uint32_t)cur * VSTG_B;

        #pragma unroll
        for (int hk = 0; hk < 2; hk++) {
            const uint32_t koffK = kbase + (uint32_t)hk * (64 * HSTR * 2);
            const uint32_t koffV = vbase + (uint32_t)hk * 128;

            // ---- S = Q K^T : 4 k16 steps over dk ----
            float s[16][4] = {};
            #pragma unroll
            for (int ks = 0; ks < 4; ks++) {
                const uint32_t ko = koffK + (uint32_t)(ks << 5);
                #pragma unroll
                for (int j = 0; j < 4; j++) {
                    uint32_t bb[4];
                    ldsm4(bb, kAdr[j] + ko);
                    mma16(s[2 * j],         qa[0][ks], bb);
                    mma16(s[2 * j + 1],     qa[0][ks], bb + 2);
                    mma16(s[8 + 2 * j],     qa[1][ks], bb);
                    mma16(s[8 + 2 * j + 1], qa[1][ks], bb + 2);
                }
            }

            // ---- P = exp(S/8)*mask; unrounded row sums ----
            #pragma unroll
            for (int mt = 0; mt < 2; mt++) {
                #pragma unroll
                for (int nt = 0; nt < 8; nt++) {
                    const int idx = mt * 8 + nt;
                    const float2 mm = *(const float2*)&maskS[cur * 128 + hk * 64 + (nt << 3) + (cq << 1)];
                    const float p00 = __expf(s[idx][0] * 0.125f) * mm.x;
                    const float p01 = __expf(s[idx][1] * 0.125f) * mm.y;
                    const float p10 = __expf(s[idx][2] * 0.125f) * mm.x;
                    const float p11 = __expf(s[idx][3] * 0.125f) * mm.y;
                    rs[mt * 2 + 0] += p00 + p01;
                    rs[mt * 2 + 1] += p10 + p11;
                    s[idx][0] = p00; s[idx][1] = p01; s[idx][2] = p10; s[idx][3] = p11;
                }
            }

            // ---- acc += P @ V ----
            #pragma unroll
            for (int t = 0; t < 4; t++) {
                const uint32_t ko = koffV + (uint32_t)(t << 5);
                uint32_t a0[4] = { packh(s[2*t][0],   s[2*t][1]),   packh(s[2*t][2],   s[2*t][3]),
                                   packh(s[2*t+1][0], s[2*t+1][1]), packh(s[2*t+1][2], s[2*t+1][3]) };
                uint32_t a1[4] = { packh(s[8+2*t][0],   s[8+2*t][1]),   packh(s[8+2*t][2],   s[8+2*t][3]),
                                   packh(s[8+2*t+1][0], s[8+2*t+1][1]), packh(s[8+2*t+1][2], s[8+2*t+1][3]) };
                #pragma unroll
                for (int j = 0; j < 4; j++) {
                    uint32_t bb[4];
                    ldsm4(bb, vAdr[j] + ko);
                    mma16(acc[2 * j],         a0, bb);
                    mma16(acc[2 * j + 1],     a0, bb + 2);
                    mma16(acc[8 + 2 * j],     a1, bb);
                    mma16(acc[8 + 2 * j + 1], a1, bb + 2);
                }
            }
        }

        // ---- pipeline refill (stage st+2) ----
        __syncthreads();
        if (st + 2 < 16) {
            const int kn = (st + 2) << 7;
            #pragma unroll
            for (int i = 0; i < 8; i++)
                cpa16(uK + kbase + (uint32_t)(tid * HSTR) * 2 + i * 16,
                      g_kh + (size_t)(bh * 2048 + kn + tid) * 64 + i * 8);
            #pragma unroll
            for (int i = 0; i < 8; i++)
                cpa16(uV + vbase + (uint32_t)(r2 * VSTR) * 2 + sBv + i * 16,
                      g_vTh + (size_t)(bh * 64 + r2) * 2048 + kn + (sBv >> 1) + i * 8);
            if (tid < 32) cpa16(uM + cur * 512 + tid * 16, mask + b * 2048 + kn + tid * 4);
        }
        CP_COMMIT();
        CP_WAIT1();
        __syncthreads();
    }

    // ---- denominator ----
    #pragma unroll
    for (int i = 0; i < 4; i++) {
        rs[i] += __shfl_xor_sync(0xffffffffu, rs[i], 1);
        rs[i] += __shfl_xor_sync(0xffffffffu, rs[i], 2);
        rs[i] = 1.0f / (rs[i] + 1e-8f);
    }

    #pragma unroll
    for (int mt = 0; mt < 2; mt++) {
        const int q_lo = q0 + qw + (mt << 4) + g;
        #pragma unroll
        for (int nt = 0; nt < 8; nt++) {
            const int idx = mt * 8 + nt;
            const int dv = (nt << 3) + (cq << 1);
            *(float2*)&out[(size_t)((b * 2048 + q_lo) * 16 + h) * 64 + dv] =
                make_float2(acc[idx][0] * rs[mt * 2], acc[idx][1] * rs[mt * 2]);
            *(float2*)&out[(size_t)((b * 2048 + q_lo + 8) * 16 + h) * 64 + dv] =
                make_float2(acc[idx][2] * rs[mt * 2 + 1], acc[idx][3] * rs[mt * 2 + 1]);
        }
    }
}

// ---------------------------------------------------------------------------
extern "C" void kernel_launch(void* const* d_in, const int* in_sizes, int n_in,
                              void* d_out, int out_size)
{
    const float* Q    = (const float*)d_in[0];
    const float* mask = (const float*)d_in[1];
    const float* Wq   = (const float*)d_in[2];
    const float* bq   = (const float*)d_in[3];
    const float* Wk   = (const float*)d_in[4];
    const float* bk   = (const float*)d_in[5];
    const float* Wv   = (const float*)d_in[6];
    const float* bv   = (const float*)d_in[7];
    float* out = (float*)d_out;

    cudaFuncSetAttribute(attn_kernel,
                         cudaFuncAttributeMaxDynamicSharedMemorySize, ATTN_SMEM_BYTES);

    round_kernel<<<dim3(4096, 4), 256>>>(Q, Wq, Wk, Wv);
    proj_kernel<<<dim3(8, 32, 3), 256>>>(bq, bk, bv);
    attn_kernel<<<dim3(16, 32), 128, ATTN_SMEM_BYTES>>>(mask, out);
}

// round 11
// speedup vs baseline: 1.0842x; 1.0842x over previous
#include <cuda_runtime.h>
#include <cuda_fp16.h>
#include <cstdint>

// Shapes: Q[2,2048,1024], mask[2,2048], W_*[1024,1024], b_*[1024], out[2,2048,1024] fp32
// Scratch (fp16): g_qh,g_kh [bh][s][64]; g_vTh [bh][64(dv)][2048(s)];
//                 g_Ah = fp16 Q-input, g_Wh = fp16 weights
__device__ __align__(16) __half g_qh [2 * 16 * 2048 * 64];
__device__ __align__(16) __half g_kh [2 * 16 * 2048 * 64];
__device__ __align__(16) __half g_vTh[2 * 16 * 64 * 2048];
__device__ __align__(16) __half g_Ah [4096 * 1024];
__device__ __align__(16) __half g_Wh [3][1024 * 1024];

// ---------------------------------------------------------------------------
// helpers
// ---------------------------------------------------------------------------
__device__ __forceinline__ uint32_t packh(float lo, float hi) {
    uint32_t d;
    asm("cvt.rn.f16x2.f32 %0, %1, %2;" : "=r"(d) : "f"(hi), "f"(lo));
    return d;
}
__device__ __forceinline__ uint32_t smem_u32(const void* p) {
    uint32_t a;
    asm("{ .reg .u64 t; cvta.to.shared.u64 t, %1; cvt.u32.u64 %0, t; }" : "=r"(a) : "l"(p));
    return a;
}
__device__ __forceinline__ void ldsm4(uint32_t* r, uint32_t addr) {
    asm volatile("ldmatrix.sync.aligned.m8n8.x4.shared.b16 {%0,%1,%2,%3}, [%4];"
                 : "=r"(r[0]), "=r"(r[1]), "=r"(r[2]), "=r"(r[3]) : "r"(addr));
}
__device__ __forceinline__ void mma16(float* c, const uint32_t* a, const uint32_t* b) {
    asm volatile(
        "mma.sync.aligned.m16n8k16.row.col.f32.f16.f16.f32 "
        "{%0,%1,%2,%3}, {%4,%5,%6,%7}, {%8,%9}, {%0,%1,%2,%3};"
        : "+f"(c[0]), "+f"(c[1]), "+f"(c[2]), "+f"(c[3])
        : "r"(a[0]), "r"(a[1]), "r"(a[2]), "r"(a[3]), "r"(b[0]), "r"(b[1]));
}
__device__ __forceinline__ void cpa16(uint32_t dst, const void* src) {
    asm volatile("cp.async.ca.shared.global [%0], [%1], 16;" :: "r"(dst), "l"(src));
}
#define CP_COMMIT() asm volatile("cp.async.commit_group;" ::: "memory")
#define CP_WAIT1()  asm volatile("cp.async.wait_group 1;" ::: "memory")

// A-operand ldmatrix byte address (16-row x k16 tile)
__device__ __forceinline__ uint32_t a_addr_h(const __half* base, int rowBase, int stride, int lane) {
    const int row = rowBase + ((lane >> 3) & 1) * 8 + (lane & 7);
    const int col = (lane >> 4) << 3;
    return smem_u32(base + row * stride + col);
}
// B-pair ldmatrix byte address -> {r0,r1}=n-group0, {r2,r3}=n-group1
__device__ __forceinline__ uint32_t b_addr_h(const __half* base, int rowBase, int stride, int lane) {
    const int sel = lane >> 3;
    const int row = rowBase + (sel >> 1) * 8 + (lane & 7);
    const int col = (sel & 1) << 3;
    return smem_u32(base + row * stride + col);
}

// ---------------------------------------------------------------------------
// fp16 pre-convert
// ---------------------------------------------------------------------------
__global__ __launch_bounds__(256)
void round_kernel(const float* __restrict__ Qin,
                  const float* __restrict__ Wq,
                  const float* __restrict__ Wk,
                  const float* __restrict__ Wv)
{
    const int i = blockIdx.x * 256 + threadIdx.x;
    const int y = blockIdx.y;
    const float* src;
    __half* dst;
    if (y == 0) { src = Qin; dst = g_Ah; }
    else        { if (i >= 262144) return;
                  src = (y == 1) ? Wq : (y == 2) ? Wk : Wv; dst = g_Wh[y - 1]; }
    const float4 v = ((const float4*)src)[i];
    ((uint2*)dst)[i] = make_uint2(packh(v.x, v.y), packh(v.z, v.w));
}

// ---------------------------------------------------------------------------
// Projection GEMM (fp16 mma) — R8 verbatim: tile M=128 N=128, K-chunk 32,
// cp.async 2-stage. 256 thr. grid = (8, 32, 3).
// ---------------------------------------------------------------------------
#define PSTR 40
#define PSTG_B (256 * PSTR * 2)

__global__ __launch_bounds__(256)
void proj_kernel(const float* __restrict__ bq,
                 const float* __restrict__ bk,
                 const float* __restrict__ bv)
{
    __shared__ __align__(16) __half sbuf[2][256 * PSTR];
    __shared__ float s_bias[128];

    const int proj = blockIdx.z;
    const __half* A = g_Ah;
    const __half* W = g_Wh[proj];
    const float* bias = (proj == 0) ? bq : (proj == 1) ? bk : bv;

    const int tid  = threadIdx.x;
    const int lane = tid & 31;
    const int w    = tid >> 5;
    const int g    = lane >> 2;
    const int cq   = lane & 3;
    const int mw   = (w & 3) << 5;
    const int nw   = (w >> 2) << 6;
    const int m0   = blockIdx.y << 7;
    const int n0   = blockIdx.x << 7;

    if (tid < 128) s_bias[tid] = bias[n0 + tid];

    const uint32_t uS = smem_u32(sbuf);

    const uint32_t aAdr0 = a_addr_h(&sbuf[0][0], mw,      PSTR, lane);
    const uint32_t aAdr1 = a_addr_h(&sbuf[0][0], mw + 16, PSTR, lane);
    uint32_t bAdr[4];
    #pragma unroll
    for (int j = 0; j < 4; j++)
        bAdr[j] = b_addr_h(&sbuf[0][128 * PSTR], nw + 16 * j, PSTR, lane);

    const __half* srcbase = (tid < 128) ? (A + (size_t)(m0 + tid) * 1024)
                                        : (W + (size_t)(n0 + tid - 128) * 1024);
    const uint32_t drow = uS + (uint32_t)(tid * PSTR) * 2;

    float acc[2][8][4] = {};

    #pragma unroll
    for (int st = 0; st < 2; st++) {
        const int k0 = st << 5;
        #pragma unroll
        for (int i = 0; i < 4; i++)
            cpa16(drow + st * PSTG_B + i * 16, srcbase + k0 + i * 8);
        CP_COMMIT();
    }

    for (int c = 0; c < 32; ++c) {
        const int st = c & 1;
        const uint32_t stoff = (uint32_t)st * PSTG_B;
        CP_WAIT1();
        __syncthreads();

        #pragma unroll
        for (int ks = 0; ks < 2; ++ks) {
            const uint32_t koff = stoff + (uint32_t)(ks << 5);
            uint32_t a0[4], a1[4];
            ldsm4(a0, aAdr0 + koff);
            ldsm4(a1, aAdr1 + koff);
            #pragma unroll
            for (int j = 0; j < 4; j++) {
                uint32_t bb[4];
                ldsm4(bb, bAdr[j] + koff);
                mma16(acc[0][2 * j],     a0, bb);
                mma16(acc[0][2 * j + 1], a0, bb + 2);
                mma16(acc[1][2 * j],     a1, bb);
                mma16(acc[1][2 * j + 1], a1, bb + 2);
            }
        }
        __syncthreads();

        if (c + 2 < 32) {
            const int k0 = (c + 2) << 5;
            #pragma unroll
            for (int i = 0; i < 4; i++)
                cpa16(drow + stoff + i * 16, srcbase + k0 + i * 8);
        }
        CP_COMMIT();
    }

    const int h = (n0 + nw) >> 6;
    #pragma unroll
    for (int mt = 0; mt < 2; mt++) {
        const int m  = m0 + mw + (mt << 4) + g;
        const int b_ = m >> 11;
        const int s  = m & 2047;
        const int bh = b_ * 16 + h;
        #pragma unroll
        for (int nt = 0; nt < 8; nt++) {
            const int col  = nw + (nt << 3) + (cq << 1);
            const int colh = col & 63;
            const float b0 = s_bias[col], b1 = s_bias[col + 1];
            if (proj < 2) {
                __half* dst = (proj == 0) ? g_qh : g_kh;
                *(uint32_t*)&dst[(size_t)(bh * 2048 + s) * 64 + colh] =
                    packh(acc[mt][nt][0] + b0, acc[mt][nt][1] + b1);
                *(uint32_t*)&dst[(size_t)(bh * 2048 + s + 8) * 64 + colh] =
                    packh(acc[mt][nt][2] + b0, acc[mt][nt][3] + b1);
            } else {
                g_vTh[(size_t)(bh * 64 + colh)     * 2048 + s]     = __float2half_rn(acc[mt][nt][0] + b0);
                g_vTh[(size_t)(bh * 64 + colh + 1) * 2048 + s]     = __float2half_rn(acc[mt][nt][1] + b1);
                g_vTh[(size_t)(bh * 64 + colh)     * 2048 + s + 8] = __float2half_rn(acc[mt][nt][2] + b0);
                g_vTh[(size_t)(bh * 64 + colh + 1) * 2048 + s + 8] = __float2half_rn(acc[mt][nt][3] + b1);
            }
        }
    }
}

// ---------------------------------------------------------------------------
// Attention v9 (fp16): R8 structure + 32-key S/PV halves to shrink the S
// transient (64->32 regs), enabling 3 blocks/SM WITHOUT spills.
// 128 thr, warp = 32q x 64 keys per kt, Q-frag reg cache, 2-stage cp.async.
// mma order identical to R8 -> bit-identical output.
// ---------------------------------------------------------------------------
#define HSTR 72
#define KSTG_B (64 * HSTR * 2)
#define ATTN_SMEM_BYTES (128 * HSTR * 2 + 4 * KSTG_B + 2 * 64 * 4)

__global__ __launch_bounds__(128, 3)
void attn_kernel(const float* __restrict__ mask, float* __restrict__ out)
{
    extern __shared__ __align__(16) __half smh[];
    __half* Qs = smh;                        // [128 q][72]
    __half* Ks = smh + 128 * HSTR;           // [2][64 key][72]
    __half* Vs = Ks + 2 * 64 * HSTR;         // [2][64 dv][72]
    float* maskS = (float*)(Vs + 2 * 64 * HSTR);   // [2][64]

    const int tid  = threadIdx.x;
    const int lane = tid & 31;
    const int w    = tid >> 5;
    const int g    = lane >> 2;
    const int cq   = lane & 3;
    const int qw   = w << 5;
    const int q0   = blockIdx.x << 7;
    const int bh   = blockIdx.y;
    const int b    = bh >> 4;
    const int h    = bh & 15;

    const uint32_t uQ = smem_u32(Qs);
    const uint32_t uK = smem_u32(Ks);
    const uint32_t uV = smem_u32(Vs);
    const uint32_t uM = smem_u32(maskS);

    uint32_t kAdr[4], vAdr[4];
    #pragma unroll
    for (int j = 0; j < 4; j++) {
        kAdr[j] = b_addr_h(Ks, 16 * j, HSTR, lane);
        vAdr[j] = b_addr_h(Vs, 16 * j, HSTR, lane);
    }

    const int r2 = tid >> 1;
    const int sB = (tid & 1) * 64;

    // ---- preload: Q + K/V tiles 0,1 + mask ----
    #pragma unroll
    for (int i = 0; i < 8; i++)
        cpa16(uQ + (uint32_t)(tid * HSTR) * 2 + i * 16,
              g_qh + (size_t)(bh * 2048 + q0 + tid) * 64 + i * 8);
    #pragma unroll
    for (int i = 0; i < 4; i++) {
        cpa16(uK + (uint32_t)(r2 * HSTR) * 2 + sB + i * 16,
              g_kh + (size_t)(bh * 2048 + r2) * 64 + (sB >> 1) + i * 8);
        cpa16(uV + (uint32_t)(r2 * HSTR) * 2 + sB + i * 16,
              g_vTh + (size_t)(bh * 64 + r2) * 2048 + (sB >> 1) + i * 8);
    }
    if (tid < 16) cpa16(uM + tid * 16, mask + b * 2048 + tid * 4);
    CP_COMMIT();
    #pragma unroll
    for (int i = 0; i < 4; i++) {
        cpa16(uK + KSTG_B + (uint32_t)(r2 * HSTR) * 2 + sB + i * 16,
              g_kh + (size_t)(bh * 2048 + 64 + r2) * 64 + (sB >> 1) + i * 8);
        cpa16(uV + KSTG_B + (uint32_t)(r2 * HSTR) * 2 + sB + i * 16,
              g_vTh + (size_t)(bh * 64 + r2) * 2048 + 64 + (sB >> 1) + i * 8);
    }
    if (tid < 16) cpa16(uM + 256 + tid * 16, mask + b * 2048 + 64 + tid * 4);
    CP_COMMIT();
    CP_WAIT1();
    __syncthreads();

    // ---- Q fragments: load once, keep in regs for all kt ----
    uint32_t qa[2][4][4];
    #pragma unroll
    for (int mt = 0; mt < 2; mt++) {
        const uint32_t qb = a_addr_h(Qs, qw + (mt << 4), HSTR, lane);
        #pragma unroll
        for (int ks = 0; ks < 4; ks++)
            ldsm4(qa[mt][ks], qb + (ks << 5));
    }

    float acc[16][4] = {};
    float rs[4] = {};

    for (int kt = 0; kt < 32; kt++) {
        const int cur = kt & 1;
        const uint32_t stoff = (uint32_t)cur * KSTG_B;

        // two 32-key halves: keeps the S transient at 8x4 = 32 regs
        #pragma unroll
        for (int hk = 0; hk < 2; hk++) {
            // ---- S = Q K^T for keys hk*32..hk*32+31 ----
            // s[mt*4 + gidx], gidx = key-group within half (global group 4hk+... no:
            // global j = 2*hk + j', groups 2j', 2j'+1 of this half)
            float s[8][4] = {};
            #pragma unroll
            for (int ks = 0; ks < 4; ks++) {
                const uint32_t koff = stoff + (uint32_t)(ks << 5);
                #pragma unroll
                for (int jp = 0; jp < 2; jp++) {
                    uint32_t bb[4];
                    ldsm4(bb, kAdr[2 * hk + jp] + koff);
                    mma16(s[2 * jp],         qa[0][ks], bb);
                    mma16(s[2 * jp + 1],     qa[0][ks], bb + 2);
                    mma16(s[4 + 2 * jp],     qa[1][ks], bb);
                    mma16(s[4 + 2 * jp + 1], qa[1][ks], bb + 2);
                }
            }

            // ---- P = exp(S/8)*mask; unrounded row sums ----
            #pragma unroll
            for (int mt = 0; mt < 2; mt++) {
                #pragma unroll
                for (int ntp = 0; ntp < 4; ntp++) {
                    const int idx = mt * 4 + ntp;
                    const int col = (hk << 5) + (ntp << 3) + (cq << 1);
                    const float2 mm = *(const float2*)&maskS[cur * 64 + col];
                    const float p00 = __expf(s[idx][0] * 0.125f) * mm.x;
                    const float p01 = __expf(s[idx][1] * 0.125f) * mm.y;
                    const float p10 = __expf(s[idx][2] * 0.125f) * mm.x;
                    const float p11 = __expf(s[idx][3] * 0.125f) * mm.y;
                    rs[mt * 2 + 0] += p00 + p01;
                    rs[mt * 2 + 1] += p10 + p11;
                    s[idx][0] = p00; s[idx][1] = p01; s[idx][2] = p10; s[idx][3] = p11;
                }
            }

            // ---- acc += P @ V for this key half (k16 steps t = 2hk, 2hk+1) ----
            #pragma unroll
            for (int tp = 0; tp < 2; tp++) {
                const uint32_t koff = stoff + (uint32_t)((2 * hk + tp) << 5);
                const int s0 = 2 * tp, s1 = 2 * tp + 1;
                uint32_t a0[4] = { packh(s[s0][0],   s[s0][1]),   packh(s[s0][2],   s[s0][3]),
                                   packh(s[s1][0],   s[s1][1]),   packh(s[s1][2],   s[s1][3]) };
                uint32_t a1[4] = { packh(s[4+s0][0], s[4+s0][1]), packh(s[4+s0][2], s[4+s0][3]),
                                   packh(s[4+s1][0], s[4+s1][1]), packh(s[4+s1][2], s[4+s1][3]) };
                #pragma unroll
                for (int j = 0; j < 4; j++) {
                    uint32_t bb[4];
                    ldsm4(bb, vAdr[j] + koff);
                    mma16(acc[2 * j],         a0, bb);
                    mma16(acc[2 * j + 1],     a0, bb + 2);
                    mma16(acc[8 + 2 * j],     a1, bb);
                    mma16(acc[8 + 2 * j + 1], a1, bb + 2);
                }
            }
        }

        // ---- pipeline refill (tile kt+2) ----
        __syncthreads();
        if (kt + 2 < 32) {
            const int kn = (kt + 2) << 6;
            #pragma unroll
            for (int i = 0; i < 4; i++) {
                cpa16(uK + stoff + (uint32_t)(r2 * HSTR) * 2 + sB + i * 16,
                      g_kh + (size_t)(bh * 2048 + kn + r2) * 64 + (sB >> 1) + i * 8);
                cpa16(uV + stoff + (uint32_t)(r2 * HSTR) * 2 + sB + i * 16,
                      g_vTh + (size_t)(bh * 64 + r2) * 2048 + kn + (sB >> 1) + i * 8);
            }
            if (tid < 16) cpa16(uM + cur * 256 + tid * 16, mask + b * 2048 + kn + tid * 4);
        }
        CP_COMMIT();
        CP_WAIT1();
        __syncthreads();
    }

    // ---- denominator ----
    #pragma unroll
    for (int i = 0; i < 4; i++) {
        rs[i] += __shfl_xor_sync(0xffffffffu, rs[i], 1);
        rs[i] += __shfl_xor_sync(0xffffffffu, rs[i], 2);
        rs[i] = 1.0f / (rs[i] + 1e-8f);
    }

    #pragma unroll
    for (int mt = 0; mt < 2; mt++) {
        const int q_lo = q0 + qw + (mt << 4) + g;
        #pragma unroll
        for (int nt = 0; nt < 8; nt++) {
            const int idx = mt * 8 + nt;
            const int dv = (nt << 3) + (cq << 1);
            *(float2*)&out[(size_t)((b * 2048 + q_lo) * 16 + h) * 64 + dv] =
                make_float2(acc[idx][0] * rs[mt * 2], acc[idx][1] * rs[mt * 2]);
            *(float2*)&out[(size_t)((b * 2048 + q_lo + 8) * 16 + h) * 64 + dv] =
                make_float2(acc[idx][2] * rs[mt * 2 + 1], acc[idx][3] * rs[mt * 2 + 1]);
        }
    }
}

// ---------------------------------------------------------------------------
extern "C" void kernel_launch(void* const* d_in, const int* in_sizes, int n_in,
                              void* d_out, int out_size)
{
    const float* Q    = (const float*)d_in[0];
    const float* mask = (const float*)d_in[1];
    const float* Wq   = (const float*)d_in[2];
    const float* bq   = (const float*)d_in[3];
    const float* Wk   = (const float*)d_in[4];
    const float* bk   = (const float*)d_in[5];
    const float* Wv   = (const float*)d_in[6];
    const float* bv   = (const float*)d_in[7];
    float* out = (float*)d_out;

    cudaFuncSetAttribute(attn_kernel,
                         cudaFuncAttributeMaxDynamicSharedMemorySize, ATTN_SMEM_BYTES);

    round_kernel<<<dim3(4096, 4), 256>>>(Q, Wq, Wk, Wv);
    proj_kernel<<<dim3(8, 32, 3), 256>>>(bq, bk, bv);
    attn_kernel<<<dim3(16, 32), 128, ATTN_SMEM_BYTES>>>(mask, out);
}

// round 12
// speedup vs baseline: 1.1989x; 1.1058x over previous
#include <cuda_runtime.h>
#include <cuda_fp16.h>
#include <cstdint>

// Shapes: Q[2,2048,1024], mask[2,2048], W_*[1024,1024], b_*[1024], out[2,2048,1024] fp32
// Scratch (fp16): g_qh,g_kh [bh][s][64]; g_vTh [bh][64(dv)][2048(s)];
//                 g_Ah = fp16 Q-input, g_Wh = fp16 weights
__device__ __align__(16) __half g_qh [2 * 16 * 2048 * 64];
__device__ __align__(16) __half g_kh [2 * 16 * 2048 * 64];
__device__ __align__(16) __half g_vTh[2 * 16 * 64 * 2048];
__device__ __align__(16) __half g_Ah [4096 * 1024];
__device__ __align__(16) __half g_Wh [3][1024 * 1024];

// ---------------------------------------------------------------------------
// helpers
// ---------------------------------------------------------------------------
__device__ __forceinline__ uint32_t packh(float lo, float hi) {
    uint32_t d;
    asm("cvt.rn.f16x2.f32 %0, %1, %2;" : "=r"(d) : "f"(hi), "f"(lo));
    return d;
}
__device__ __forceinline__ uint32_t smem_u32(const void* p) {
    uint32_t a;
    asm("{ .reg .u64 t; cvta.to.shared.u64 t, %1; cvt.u32.u64 %0, t; }" : "=r"(a) : "l"(p));
    return a;
}
__device__ __forceinline__ void ldsm4(uint32_t* r, uint32_t addr) {
    asm volatile("ldmatrix.sync.aligned.m8n8.x4.shared.b16 {%0,%1,%2,%3}, [%4];"
                 : "=r"(r[0]), "=r"(r[1]), "=r"(r[2]), "=r"(r[3]) : "r"(addr));
}
__device__ __forceinline__ void mma16(float* c, const uint32_t* a, const uint32_t* b) {
    asm volatile(
        "mma.sync.aligned.m16n8k16.row.col.f32.f16.f16.f32 "
        "{%0,%1,%2,%3}, {%4,%5,%6,%7}, {%8,%9}, {%0,%1,%2,%3};"
        : "+f"(c[0]), "+f"(c[1]), "+f"(c[2]), "+f"(c[3])
        : "r"(a[0]), "r"(a[1]), "r"(a[2]), "r"(a[3]), "r"(b[0]), "r"(b[1]));
}
__device__ __forceinline__ void cpa16(uint32_t dst, const void* src) {
    asm volatile("cp.async.cg.shared.global [%0], [%1], 16;" :: "r"(dst), "l"(src));
}
#define CP_COMMIT() asm volatile("cp.async.commit_group;" ::: "memory")
#define CP_WAIT1()  asm volatile("cp.async.wait_group 1;" ::: "memory")

// A-operand ldmatrix byte address (16-row x k16 tile)
__device__ __forceinline__ uint32_t a_addr_h(const __half* base, int rowBase, int stride, int lane) {
    const int row = rowBase + ((lane >> 3) & 1) * 8 + (lane & 7);
    const int col = (lane >> 4) << 3;
    return smem_u32(base + row * stride + col);
}
// B-pair ldmatrix byte address -> {r0,r1}=n-group0, {r2,r3}=n-group1
__device__ __forceinline__ uint32_t b_addr_h(const __half* base, int rowBase, int stride, int lane) {
    const int sel = lane >> 3;
    const int row = rowBase + (sel >> 1) * 8 + (lane & 7);
    const int col = (sel & 1) << 3;
    return smem_u32(base + row * stride + col);
}

// ---------------------------------------------------------------------------
// fp16 pre-convert
// ---------------------------------------------------------------------------
__global__ __launch_bounds__(256)
void round_kernel(const float* __restrict__ Qin,
                  const float* __restrict__ Wq,
                  const float* __restrict__ Wk,
                  const float* __restrict__ Wv)
{
    const int i = blockIdx.x * 256 + threadIdx.x;
    const int y = blockIdx.y;
    const float* src;
    __half* dst;
    if (y == 0) { src = Qin; dst = g_Ah; }
    else        { if (i >= 262144) return;
                  src = (y == 1) ? Wq : (y == 2) ? Wk : Wv; dst = g_Wh[y - 1]; }
    const float4 v = ((const float4*)src)[i];
    ((uint2*)dst)[i] = make_uint2(packh(v.x, v.y), packh(v.z, v.w));
}

// ---------------------------------------------------------------------------
// Projection GEMM (fp16 mma): tile M=128 N=128, K-chunk 64 (4 k16 steps),
// cp.async 2-stage, 16 mainloop iterations. 256 thr. grid = (8, 32, 3).
// Same k-accumulation order as K-chunk-32 version -> bit-identical output.
// ---------------------------------------------------------------------------
#define PSTR 72
#define PSTG_B (256 * PSTR * 2)

__global__ __launch_bounds__(256, 2)
void proj_kernel(const float* __restrict__ bq,
                 const float* __restrict__ bk,
                 const float* __restrict__ bv)
{
    __shared__ __align__(16) __half sbuf[2][256 * PSTR];
    __shared__ float s_bias[128];

    const int proj = blockIdx.z;
    const __half* A = g_Ah;
    const __half* W = g_Wh[proj];
    const float* bias = (proj == 0) ? bq : (proj == 1) ? bk : bv;

    const int tid  = threadIdx.x;
    const int lane = tid & 31;
    const int w    = tid >> 5;
    const int g    = lane >> 2;
    const int cq   = lane & 3;
    const int mw   = (w & 3) << 5;
    const int nw   = (w >> 2) << 6;
    const int m0   = blockIdx.y << 7;
    const int n0   = blockIdx.x << 7;

    if (tid < 128) s_bias[tid] = bias[n0 + tid];

    const uint32_t uS = smem_u32(sbuf);

    const uint32_t aAdr0 = a_addr_h(&sbuf[0][0], mw,      PSTR, lane);
    const uint32_t aAdr1 = a_addr_h(&sbuf[0][0], mw + 16, PSTR, lane);
    uint32_t bAdr[4];
    #pragma unroll
    for (int j = 0; j < 4; j++)
        bAdr[j] = b_addr_h(&sbuf[0][128 * PSTR], nw + 16 * j, PSTR, lane);

    const __half* srcbase = (tid < 128) ? (A + (size_t)(m0 + tid) * 1024)
                                        : (W + (size_t)(n0 + tid - 128) * 1024);
    const uint32_t drow = uS + (uint32_t)(tid * PSTR) * 2;

    float acc[2][8][4] = {};

    #pragma unroll
    for (int st = 0; st < 2; st++) {
        const int k0 = st << 6;
        #pragma unroll
        for (int i = 0; i < 8; i++)
            cpa16(drow + st * PSTG_B + i * 16, srcbase + k0 + i * 8);
        CP_COMMIT();
    }

    for (int c = 0; c < 16; ++c) {
        const int st = c & 1;
        const uint32_t stoff = (uint32_t)st * PSTG_B;
        CP_WAIT1();
        __syncthreads();

        #pragma unroll
        for (int ks = 0; ks < 4; ++ks) {
            const uint32_t koff = stoff + (uint32_t)(ks << 5);
            uint32_t a0[4], a1[4];
            ldsm4(a0, aAdr0 + koff);
            ldsm4(a1, aAdr1 + koff);
            #pragma unroll
            for (int j = 0; j < 4; j++) {
                uint32_t bb[4];
                ldsm4(bb, bAdr[j] + koff);
                mma16(acc[0][2 * j],     a0, bb);
                mma16(acc[0][2 * j + 1], a0, bb + 2);
                mma16(acc[1][2 * j],     a1, bb);
                mma16(acc[1][2 * j + 1], a1, bb + 2);
            }
        }
        __syncthreads();

        if (c + 2 < 16) {
            const int k0 = (c + 2) << 6;
            #pragma unroll
            for (int i = 0; i < 8; i++)
                cpa16(drow + stoff + i * 16, srcbase + k0 + i * 8);
        }
        CP_COMMIT();
    }

    const int h = (n0 + nw) >> 6;
    #pragma unroll
    for (int mt = 0; mt < 2; mt++) {
        const int m  = m0 + mw + (mt << 4) + g;
        const int b_ = m >> 11;
        const int s  = m & 2047;
        const int bh = b_ * 16 + h;
        #pragma unroll
        for (int nt = 0; nt < 8; nt++) {
            const int col  = nw + (nt << 3) + (cq << 1);
            const int colh = col & 63;
            const float b0 = s_bias[col], b1 = s_bias[col + 1];
            if (proj < 2) {
                __half* dst = (proj == 0) ? g_qh : g_kh;
                *(uint32_t*)&dst[(size_t)(bh * 2048 + s) * 64 + colh] =
                    packh(acc[mt][nt][0] + b0, acc[mt][nt][1] + b1);
                *(uint32_t*)&dst[(size_t)(bh * 2048 + s + 8) * 64 + colh] =
                    packh(acc[mt][nt][2] + b0, acc[mt][nt][3] + b1);
            } else {
                g_vTh[(size_t)(bh * 64 + colh)     * 2048 + s]     = __float2half_rn(acc[mt][nt][0] + b0);
                g_vTh[(size_t)(bh * 64 + colh + 1) * 2048 + s]     = __float2half_rn(acc[mt][nt][1] + b1);
                g_vTh[(size_t)(bh * 64 + colh)     * 2048 + s + 8] = __float2half_rn(acc[mt][nt][2] + b0);
                g_vTh[(size_t)(bh * 64 + colh + 1) * 2048 + s + 8] = __float2half_rn(acc[mt][nt][3] + b1);
            }
        }
    }
}

// ---------------------------------------------------------------------------
// Attention (fp16) — R8 VERBATIM (known-best config): 128 thr, 2 blocks/SM,
// warp = 32q x 64 keys, Q-frag reg cache, 64-key 2-stage cp.async pipeline,
// PV A-fragments = f16x2 packs of the exp'd S accumulator.
// ---------------------------------------------------------------------------
#define HSTR 72
#define KSTG_B (64 * HSTR * 2)
#define ATTN_SMEM_BYTES (128 * HSTR * 2 + 4 * KSTG_B + 2 * 64 * 4)

__global__ __launch_bounds__(128, 2)
void attn_kernel(const float* __restrict__ mask, float* __restrict__ out)
{
    extern __shared__ __align__(16) __half smh[];
    __half* Qs = smh;                        // [128 q][72]
    __half* Ks = smh + 128 * HSTR;           // [2][64 key][72]
    __half* Vs = Ks + 2 * 64 * HSTR;         // [2][64 dv][72]
    float* maskS = (float*)(Vs + 2 * 64 * HSTR);   // [2][64]

    const int tid  = threadIdx.x;
    const int lane = tid & 31;
    const int w    = tid >> 5;
    const int g    = lane >> 2;
    const int cq   = lane & 3;
    const int qw   = w << 5;
    const int q0   = blockIdx.x << 7;
    const int bh   = blockIdx.y;
    const int b    = bh >> 4;
    const int h    = bh & 15;

    const uint32_t uQ = smem_u32(Qs);
    const uint32_t uK = smem_u32(Ks);
    const uint32_t uV = smem_u32(Vs);
    const uint32_t uM = smem_u32(maskS);

    uint32_t kAdr[4], vAdr[4];
    #pragma unroll
    for (int j = 0; j < 4; j++) {
        kAdr[j] = b_addr_h(Ks, 16 * j, HSTR, lane);
        vAdr[j] = b_addr_h(Vs, 16 * j, HSTR, lane);
    }

    const int r2 = tid >> 1;
    const int sB = (tid & 1) * 64;

    // ---- preload: Q + K/V tiles 0,1 + mask ----
    #pragma unroll
    for (int i = 0; i < 8; i++)
        cpa16(uQ + (uint32_t)(tid * HSTR) * 2 + i * 16,
              g_qh + (size_t)(bh * 2048 + q0 + tid) * 64 + i * 8);
    #pragma unroll
    for (int i = 0; i < 4; i++) {
        cpa16(uK + (uint32_t)(r2 * HSTR) * 2 + sB + i * 16,
              g_kh + (size_t)(bh * 2048 + r2) * 64 + (sB >> 1) + i * 8);
        cpa16(uV + (uint32_t)(r2 * HSTR) * 2 + sB + i * 16,
              g_vTh + (size_t)(bh * 64 + r2) * 2048 + (sB >> 1) + i * 8);
    }
    if (tid < 16) cpa16(uM + tid * 16, mask + b * 2048 + tid * 4);
    CP_COMMIT();
    #pragma unroll
    for (int i = 0; i < 4; i++) {
        cpa16(uK + KSTG_B + (uint32_t)(r2 * HSTR) * 2 + sB + i * 16,
              g_kh + (size_t)(bh * 2048 + 64 + r2) * 64 + (sB >> 1) + i * 8);
        cpa16(uV + KSTG_B + (uint32_t)(r2 * HSTR) * 2 + sB + i * 16,
              g_vTh + (size_t)(bh * 64 + r2) * 2048 + 64 + (sB >> 1) + i * 8);
    }
    if (tid < 16) cpa16(uM + 256 + tid * 16, mask + b * 2048 + 64 + tid * 4);
    CP_COMMIT();
    CP_WAIT1();
    __syncthreads();

    // ---- Q fragments: load once, keep in regs for all kt ----
    uint32_t qa[2][4][4];
    #pragma unroll
    for (int mt = 0; mt < 2; mt++) {
        const uint32_t qb = a_addr_h(Qs, qw + (mt << 4), HSTR, lane);
        #pragma unroll
        for (int ks = 0; ks < 4; ks++)
            ldsm4(qa[mt][ks], qb + (ks << 5));
    }

    float acc[16][4] = {};
    float rs[4] = {};

    for (int kt = 0; kt < 32; kt++) {
        const int cur = kt & 1;
        const uint32_t stoff = (uint32_t)cur * KSTG_B;

        // ---- S = Q K^T : 4 k16 steps over dk ----
        float s[16][4] = {};
        #pragma unroll
        for (int ks = 0; ks < 4; ks++) {
            const uint32_t koff = stoff + (uint32_t)(ks << 5);
            #pragma unroll
            for (int j = 0; j < 4; j++) {
                uint32_t bb[4];
                ldsm4(bb, kAdr[j] + koff);
                mma16(s[2 * j],         qa[0][ks], bb);
                mma16(s[2 * j + 1],     qa[0][ks], bb + 2);
                mma16(s[8 + 2 * j],     qa[1][ks], bb);
                mma16(s[8 + 2 * j + 1], qa[1][ks], bb + 2);
            }
        }

        // ---- P = exp(S/8)*mask; unrounded row sums ----
        #pragma unroll
        for (int mt = 0; mt < 2; mt++) {
            #pragma unroll
            for (int nt = 0; nt < 8; nt++) {
                const int idx = mt * 8 + nt;
                const float2 mm = *(const float2*)&maskS[cur * 64 + (nt << 3) + (cq << 1)];
                const float p00 = __expf(s[idx][0] * 0.125f) * mm.x;
                const float p01 = __expf(s[idx][1] * 0.125f) * mm.y;
                const float p10 = __expf(s[idx][2] * 0.125f) * mm.x;
                const float p11 = __expf(s[idx][3] * 0.125f) * mm.y;
                rs[mt * 2 + 0] += p00 + p01;
                rs[mt * 2 + 1] += p10 + p11;
                s[idx][0] = p00; s[idx][1] = p01; s[idx][2] = p10; s[idx][3] = p11;
            }
        }

        // ---- acc += P @ V : A = f16x2 packs of s (native pairing) ----
        #pragma unroll
        for (int t = 0; t < 4; t++) {
            const uint32_t koff = stoff + (uint32_t)(t << 5);
            uint32_t a0[4] = { packh(s[2*t][0],   s[2*t][1]),   packh(s[2*t][2],   s[2*t][3]),
                               packh(s[2*t+1][0], s[2*t+1][1]), packh(s[2*t+1][2], s[2*t+1][3]) };
            uint32_t a1[4] = { packh(s[8+2*t][0],   s[8+2*t][1]),   packh(s[8+2*t][2],   s[8+2*t][3]),
                               packh(s[8+2*t+1][0], s[8+2*t+1][1]), packh(s[8+2*t+1][2], s[8+2*t+1][3]) };
            #pragma unroll
            for (int j = 0; j < 4; j++) {
                uint32_t bb[4];
                ldsm4(bb, vAdr[j] + koff);
                mma16(acc[2 * j],         a0, bb);
                mma16(acc[2 * j + 1],     a0, bb + 2);
                mma16(acc[8 + 2 * j],     a1, bb);
                mma16(acc[8 + 2 * j + 1], a1, bb + 2);
            }
        }

        // ---- pipeline refill (tile kt+2) ----
        __syncthreads();
        if (kt + 2 < 32) {
            const int kn = (kt + 2) << 6;
            #pragma unroll
            for (int i = 0; i < 4; i++) {
                cpa16(uK + stoff + (uint32_t)(r2 * HSTR) * 2 + sB + i * 16,
                      g_kh + (size_t)(bh * 2048 + kn + r2) * 64 + (sB >> 1) + i * 8);
                cpa16(uV + stoff + (uint32_t)(r2 * HSTR) * 2 + sB + i * 16,
                      g_vTh + (size_t)(bh * 64 + r2) * 2048 + kn + (sB >> 1) + i * 8);
            }
            if (tid < 16) cpa16(uM + cur * 256 + tid * 16, mask + b * 2048 + kn + tid * 4);
        }
        CP_COMMIT();
        CP_WAIT1();
        __syncthreads();
    }

    // ---- denominator ----
    #pragma unroll
    for (int i = 0; i < 4; i++) {
        rs[i] += __shfl_xor_sync(0xffffffffu, rs[i], 1);
        rs[i] += __shfl_xor_sync(0xffffffffu, rs[i], 2);
        rs[i] = 1.0f / (rs[i] + 1e-8f);
    }

    #pragma unroll
    for (int mt = 0; mt < 2; mt++) {
        const int q_lo = q0 + qw + (mt << 4) + g;
        #pragma unroll
        for (int nt = 0; nt < 8; nt++) {
            const int idx = mt * 8 + nt;
            const int dv = (nt << 3) + (cq << 1);
            *(float2*)&out[(size_t)((b * 2048 + q_lo) * 16 + h) * 64 + dv] =
                make_float2(acc[idx][0] * rs[mt * 2], acc[idx][1] * rs[mt * 2]);
            *(float2*)&out[(size_t)((b * 2048 + q_lo + 8) * 16 + h) * 64 + dv] =
                make_float2(acc[idx][2] * rs[mt * 2 + 1], acc[idx][3] * rs[mt * 2 + 1]);
        }
    }
}

// ---------------------------------------------------------------------------
extern "C" void kernel_launch(void* const* d_in, const int* in_sizes, int n_in,
                              void* d_out, int out_size)
{
    const float* Q    = (const float*)d_in[0];
    const float* mask = (const float*)d_in[1];
    const float* Wq   = (const float*)d_in[2];
    const float* bq   = (const float*)d_in[3];
    const float* Wk   = (const float*)d_in[4];
    const float* bk   = (const float*)d_in[5];
    const float* Wv   = (const float*)d_in[6];
    const float* bv   = (const float*)d_in[7];
    float* out = (float*)d_out;

    cudaFuncSetAttribute(attn_kernel,
                         cudaFuncAttributeMaxDynamicSharedMemorySize, ATTN_SMEM_BYTES);

    round_kernel<<<dim3(4096, 4), 256>>>(Q, Wq, Wk, Wv);
    proj_kernel<<<dim3(8, 32, 3), 256>>>(bq, bk, bv);
    attn_kernel<<<dim3(16, 32), 128, ATTN_SMEM_BYTES>>>(mask, out);
}

// round 13
// speedup vs baseline: 1.2321x; 1.0277x over previous
#include <cuda_runtime.h>
#include <cuda_fp16.h>
#include <cstdint>

// Shapes: Q[2,2048,1024], mask[2,2048], W_*[1024,1024], b_*[1024], out[2,2048,1024] fp32
// Scratch (fp16): g_qh,g_kh [bh][s][64]; g_vTh [bh][64(dv)][2048(s)];
//                 g_Ah = fp16 Q-input, g_Wh = fp16 weights
__device__ __align__(16) __half g_qh [2 * 16 * 2048 * 64];
__device__ __align__(16) __half g_kh [2 * 16 * 2048 * 64];
__device__ __align__(16) __half g_vTh[2 * 16 * 64 * 2048];
__device__ __align__(16) __half g_Ah [4096 * 1024];
__device__ __align__(16) __half g_Wh [3][1024 * 1024];

// ---------------------------------------------------------------------------
// helpers
// ---------------------------------------------------------------------------
__device__ __forceinline__ uint32_t packh(float lo, float hi) {
    uint32_t d;
    asm("cvt.rn.f16x2.f32 %0, %1, %2;" : "=r"(d) : "f"(hi), "f"(lo));
    return d;
}
__device__ __forceinline__ uint32_t smem_u32(const void* p) {
    uint32_t a;
    asm("{ .reg .u64 t; cvta.to.shared.u64 t, %1; cvt.u32.u64 %0, t; }" : "=r"(a) : "l"(p));
    return a;
}
__device__ __forceinline__ void ldsm4(uint32_t* r, uint32_t addr) {
    asm volatile("ldmatrix.sync.aligned.m8n8.x4.shared.b16 {%0,%1,%2,%3}, [%4];"
                 : "=r"(r[0]), "=r"(r[1]), "=r"(r[2]), "=r"(r[3]) : "r"(addr));
}
__device__ __forceinline__ void mma16(float* c, const uint32_t* a, const uint32_t* b) {
    asm volatile(
        "mma.sync.aligned.m16n8k16.row.col.f32.f16.f16.f32 "
        "{%0,%1,%2,%3}, {%4,%5,%6,%7}, {%8,%9}, {%0,%1,%2,%3};"
        : "+f"(c[0]), "+f"(c[1]), "+f"(c[2]), "+f"(c[3])
        : "r"(a[0]), "r"(a[1]), "r"(a[2]), "r"(a[3]), "r"(b[0]), "r"(b[1]));
}
__device__ __forceinline__ void cpa16(uint32_t dst, const void* src) {
    asm volatile("cp.async.cg.shared.global [%0], [%1], 16;" :: "r"(dst), "l"(src));
}
#define CP_COMMIT() asm volatile("cp.async.commit_group;" ::: "memory")
#define CP_WAIT1()  asm volatile("cp.async.wait_group 1;" ::: "memory")

// A-operand ldmatrix byte address (16-row x k16 tile)
__device__ __forceinline__ uint32_t a_addr_h(const __half* base, int rowBase, int stride, int lane) {
    const int row = rowBase + ((lane >> 3) & 1) * 8 + (lane & 7);
    const int col = (lane >> 4) << 3;
    return smem_u32(base + row * stride + col);
}
// B-pair ldmatrix byte address -> {r0,r1}=n-group0, {r2,r3}=n-group1
__device__ __forceinline__ uint32_t b_addr_h(const __half* base, int rowBase, int stride, int lane) {
    const int sel = lane >> 3;
    const int row = rowBase + (sel >> 1) * 8 + (lane & 7);
    const int col = (sel & 1) << 3;
    return smem_u32(base + row * stride + col);
}

// ---------------------------------------------------------------------------
// fp16 pre-convert
// ---------------------------------------------------------------------------
__global__ __launch_bounds__(256)
void round_kernel(const float* __restrict__ Qin,
                  const float* __restrict__ Wq,
                  const float* __restrict__ Wk,
                  const float* __restrict__ Wv)
{
    const int i = blockIdx.x * 256 + threadIdx.x;
    const int y = blockIdx.y;
    const float* src;
    __half* dst;
    if (y == 0) { src = Qin; dst = g_Ah; }
    else        { if (i >= 262144) return;
                  src = (y == 1) ? Wq : (y == 2) ? Wk : Wv; dst = g_Wh[y - 1]; }
    const float4 v = ((const float4*)src)[i];
    ((uint2*)dst)[i] = make_uint2(packh(v.x, v.y), packh(v.z, v.w));
}

// ---------------------------------------------------------------------------
// Projection GEMM (fp16 mma) — R12 verbatim: tile M=128 N=128, K-chunk 64,
// cp.async 2-stage, 16 mainloop iterations. 256 thr. grid = (8, 32, 3).
// ---------------------------------------------------------------------------
#define PSTR 72
#define PSTG_B (256 * PSTR * 2)

__global__ __launch_bounds__(256, 2)
void proj_kernel(const float* __restrict__ bq,
                 const float* __restrict__ bk,
                 const float* __restrict__ bv)
{
    __shared__ __align__(16) __half sbuf[2][256 * PSTR];
    __shared__ float s_bias[128];

    const int proj = blockIdx.z;
    const __half* A = g_Ah;
    const __half* W = g_Wh[proj];
    const float* bias = (proj == 0) ? bq : (proj == 1) ? bk : bv;

    const int tid  = threadIdx.x;
    const int lane = tid & 31;
    const int w    = tid >> 5;
    const int g    = lane >> 2;
    const int cq   = lane & 3;
    const int mw   = (w & 3) << 5;
    const int nw   = (w >> 2) << 6;
    const int m0   = blockIdx.y << 7;
    const int n0   = blockIdx.x << 7;

    if (tid < 128) s_bias[tid] = bias[n0 + tid];

    const uint32_t uS = smem_u32(sbuf);

    const uint32_t aAdr0 = a_addr_h(&sbuf[0][0], mw,      PSTR, lane);
    const uint32_t aAdr1 = a_addr_h(&sbuf[0][0], mw + 16, PSTR, lane);
    uint32_t bAdr[4];
    #pragma unroll
    for (int j = 0; j < 4; j++)
        bAdr[j] = b_addr_h(&sbuf[0][128 * PSTR], nw + 16 * j, PSTR, lane);

    const __half* srcbase = (tid < 128) ? (A + (size_t)(m0 + tid) * 1024)
                                        : (W + (size_t)(n0 + tid - 128) * 1024);
    const uint32_t drow = uS + (uint32_t)(tid * PSTR) * 2;

    float acc[2][8][4] = {};

    #pragma unroll
    for (int st = 0; st < 2; st++) {
        const int k0 = st << 6;
        #pragma unroll
        for (int i = 0; i < 8; i++)
            cpa16(drow + st * PSTG_B + i * 16, srcbase + k0 + i * 8);
        CP_COMMIT();
    }

    for (int c = 0; c < 16; ++c) {
        const int st = c & 1;
        const uint32_t stoff = (uint32_t)st * PSTG_B;
        CP_WAIT1();
        __syncthreads();

        #pragma unroll
        for (int ks = 0; ks < 4; ++ks) {
            const uint32_t koff = stoff + (uint32_t)(ks << 5);
            uint32_t a0[4], a1[4];
            ldsm4(a0, aAdr0 + koff);
            ldsm4(a1, aAdr1 + koff);
            #pragma unroll
            for (int j = 0; j < 4; j++) {
                uint32_t bb[4];
                ldsm4(bb, bAdr[j] + koff);
                mma16(acc[0][2 * j],     a0, bb);
                mma16(acc[0][2 * j + 1], a0, bb + 2);
                mma16(acc[1][2 * j],     a1, bb);
                mma16(acc[1][2 * j + 1], a1, bb + 2);
            }
        }
        __syncthreads();

        if (c + 2 < 16) {
            const int k0 = (c + 2) << 6;
            #pragma unroll
            for (int i = 0; i < 8; i++)
                cpa16(drow + stoff + i * 16, srcbase + k0 + i * 8);
        }
        CP_COMMIT();
    }

    const int h = (n0 + nw) >> 6;
    #pragma unroll
    for (int mt = 0; mt < 2; mt++) {
        const int m  = m0 + mw + (mt << 4) + g;
        const int b_ = m >> 11;
        const int s  = m & 2047;
        const int bh = b_ * 16 + h;
        #pragma unroll
        for (int nt = 0; nt < 8; nt++) {
            const int col  = nw + (nt << 3) + (cq << 1);
            const int colh = col & 63;
            const float b0 = s_bias[col], b1 = s_bias[col + 1];
            if (proj < 2) {
                __half* dst = (proj == 0) ? g_qh : g_kh;
                *(uint32_t*)&dst[(size_t)(bh * 2048 + s) * 64 + colh] =
                    packh(acc[mt][nt][0] + b0, acc[mt][nt][1] + b1);
                *(uint32_t*)&dst[(size_t)(bh * 2048 + s + 8) * 64 + colh] =
                    packh(acc[mt][nt][2] + b0, acc[mt][nt][3] + b1);
            } else {
                g_vTh[(size_t)(bh * 64 + colh)     * 2048 + s]     = __float2half_rn(acc[mt][nt][0] + b0);
                g_vTh[(size_t)(bh * 64 + colh + 1) * 2048 + s]     = __float2half_rn(acc[mt][nt][1] + b1);
                g_vTh[(size_t)(bh * 64 + colh)     * 2048 + s + 8] = __float2half_rn(acc[mt][nt][2] + b0);
                g_vTh[(size_t)(bh * 64 + colh + 1) * 2048 + s + 8] = __float2half_rn(acc[mt][nt][3] + b1);
            }
        }
    }
}

// ---------------------------------------------------------------------------
// Attention v10 (fp16): 256 thr (8 warps), warp = 16q x 64 keys, 128-q block,
// 2 blocks/SM -> 4 warps/SMSP. Per-warp regs ~110 (acc32+s32+qa16) -> no spill
// under the 128-reg cap. Same mma order per output element as R8/R12.
// ---------------------------------------------------------------------------
#define HSTR 72
#define KSTG_B (64 * HSTR * 2)
#define ATTN_SMEM_BYTES (128 * HSTR * 2 + 4 * KSTG_B + 2 * 64 * 4)

__global__ __launch_bounds__(256, 2)
void attn_kernel(const float* __restrict__ mask, float* __restrict__ out)
{
    extern __shared__ __align__(16) __half smh[];
    __half* Qs = smh;                        // [128 q][72]
    __half* Ks = smh + 128 * HSTR;           // [2][64 key][72]
    __half* Vs = Ks + 2 * 64 * HSTR;         // [2][64 dv][72]
    float* maskS = (float*)(Vs + 2 * 64 * HSTR);   // [2][64]

    const int tid  = threadIdx.x;
    const int lane = tid & 31;
    const int w    = tid >> 5;               // 0..7
    const int g    = lane >> 2;
    const int cq   = lane & 3;
    const int qw   = w << 4;                 // warp q offset (0..112)
    const int q0   = blockIdx.x << 7;
    const int bh   = blockIdx.y;
    const int b    = bh >> 4;
    const int h    = bh & 15;

    const uint32_t uQ = smem_u32(Qs);
    const uint32_t uK = smem_u32(Ks);
    const uint32_t uV = smem_u32(Vs);
    const uint32_t uM = smem_u32(maskS);

    uint32_t kAdr[4], vAdr[4];
    #pragma unroll
    for (int j = 0; j < 4; j++) {
        kAdr[j] = b_addr_h(Ks, 16 * j, HSTR, lane);
        vAdr[j] = b_addr_h(Vs, 16 * j, HSTR, lane);
    }

    // loaders (256 threads): Q: thread -> (row, 64B half); K/V: (row, 32B quarter)
    const int qrow = tid >> 1;             // 0..127
    const int qB   = (tid & 1) * 64;       // byte offset in 128B row
    const int kvrow = tid >> 2;            // 0..63
    const int kvB   = (tid & 3) * 32;      // byte offset in 128B row

    // ---- preload: Q + K/V tiles 0,1 + mask ----
    #pragma unroll
    for (int i = 0; i < 4; i++)
        cpa16(uQ + (uint32_t)(qrow * HSTR) * 2 + qB + i * 16,
              g_qh + (size_t)(bh * 2048 + q0 + qrow) * 64 + (qB >> 1) + i * 8);
    #pragma unroll
    for (int i = 0; i < 2; i++) {
        cpa16(uK + (uint32_t)(kvrow * HSTR) * 2 + kvB + i * 16,
              g_kh + (size_t)(bh * 2048 + kvrow) * 64 + (kvB >> 1) + i * 8);
        cpa16(uV + (uint32_t)(kvrow * HSTR) * 2 + kvB + i * 16,
              g_vTh + (size_t)(bh * 64 + kvrow) * 2048 + (kvB >> 1) + i * 8);
    }
    if (tid < 16) cpa16(uM + tid * 16, mask + b * 2048 + tid * 4);
    CP_COMMIT();
    #pragma unroll
    for (int i = 0; i < 2; i++) {
        cpa16(uK + KSTG_B + (uint32_t)(kvrow * HSTR) * 2 + kvB + i * 16,
              g_kh + (size_t)(bh * 2048 + 64 + kvrow) * 64 + (kvB >> 1) + i * 8);
        cpa16(uV + KSTG_B + (uint32_t)(kvrow * HSTR) * 2 + kvB + i * 16,
              g_vTh + (size_t)(bh * 64 + kvrow) * 2048 + 64 + (kvB >> 1) + i * 8);
    }
    if (tid < 16) cpa16(uM + 256 + tid * 16, mask + b * 2048 + 64 + tid * 4);
    CP_COMMIT();
    CP_WAIT1();
    __syncthreads();

    // ---- Q fragments: load once, keep in regs for all kt (16 regs) ----
    uint32_t qa[4][4];
    {
        const uint32_t qb = a_addr_h(Qs, qw, HSTR, lane);
        #pragma unroll
        for (int ks = 0; ks < 4; ks++)
            ldsm4(qa[ks], qb + (ks << 5));
    }

    float acc[8][4] = {};
    float rs[2] = {};

    for (int kt = 0; kt < 32; kt++) {
        const int cur = kt & 1;
        const uint32_t stoff = (uint32_t)cur * KSTG_B;

        // ---- S = Q K^T : 4 k16 steps over dk ----
        float s[8][4] = {};
        #pragma unroll
        for (int ks = 0; ks < 4; ks++) {
            const uint32_t koff = stoff + (uint32_t)(ks << 5);
            #pragma unroll
            for (int j = 0; j < 4; j++) {
                uint32_t bb[4];
                ldsm4(bb, kAdr[j] + koff);
                mma16(s[2 * j],     qa[ks], bb);
                mma16(s[2 * j + 1], qa[ks], bb + 2);
            }
        }

        // ---- P = exp(S/8)*mask; unrounded row sums ----
        #pragma unroll
        for (int nt = 0; nt < 8; nt++) {
            const float2 mm = *(const float2*)&maskS[cur * 64 + (nt << 3) + (cq << 1)];
            const float p00 = __expf(s[nt][0] * 0.125f) * mm.x;
            const float p01 = __expf(s[nt][1] * 0.125f) * mm.y;
            const float p10 = __expf(s[nt][2] * 0.125f) * mm.x;
            const float p11 = __expf(s[nt][3] * 0.125f) * mm.y;
            rs[0] += p00 + p01;
            rs[1] += p10 + p11;
            s[nt][0] = p00; s[nt][1] = p01; s[nt][2] = p10; s[nt][3] = p11;
        }

        // ---- acc += P @ V : A = f16x2 packs of s (native pairing) ----
        #pragma unroll
        for (int t = 0; t < 4; t++) {
            const uint32_t koff = stoff + (uint32_t)(t << 5);
            uint32_t a[4] = { packh(s[2*t][0],   s[2*t][1]),   packh(s[2*t][2],   s[2*t][3]),
                              packh(s[2*t+1][0], s[2*t+1][1]), packh(s[2*t+1][2], s[2*t+1][3]) };
            #pragma unroll
            for (int j = 0; j < 4; j++) {
                uint32_t bb[4];
                ldsm4(bb, vAdr[j] + koff);
                mma16(acc[2 * j],     a, bb);
                mma16(acc[2 * j + 1], a, bb + 2);
            }
        }

        // ---- pipeline refill (tile kt+2) ----
        __syncthreads();
        if (kt + 2 < 32) {
            const int kn = (kt + 2) << 6;
            #pragma unroll
            for (int i = 0; i < 2; i++) {
                cpa16(uK + stoff + (uint32_t)(kvrow * HSTR) * 2 + kvB + i * 16,
                      g_kh + (size_t)(bh * 2048 + kn + kvrow) * 64 + (kvB >> 1) + i * 8);
                cpa16(uV + stoff + (uint32_t)(kvrow * HSTR) * 2 + kvB + i * 16,
                      g_vTh + (size_t)(bh * 64 + kvrow) * 2048 + kn + (kvB >> 1) + i * 8);
            }
            if (tid < 16) cpa16(uM + cur * 256 + tid * 16, mask + b * 2048 + kn + tid * 4);
        }
        CP_COMMIT();
        CP_WAIT1();
        __syncthreads();
    }

    // ---- denominator: reduce across the 4 cq lanes ----
    #pragma unroll
    for (int i = 0; i < 2; i++) {
        rs[i] += __shfl_xor_sync(0xffffffffu, rs[i], 1);
        rs[i] += __shfl_xor_sync(0xffffffffu, rs[i], 2);
        rs[i] = 1.0f / (rs[i] + 1e-8f);
    }

    const int q_lo = q0 + qw + g;
    #pragma unroll
    for (int nt = 0; nt < 8; nt++) {
        const int dv = (nt << 3) + (cq << 1);
        *(float2*)&out[(size_t)((b * 2048 + q_lo) * 16 + h) * 64 + dv] =
            make_float2(acc[nt][0] * rs[0], acc[nt][1] * rs[0]);
        *(float2*)&out[(size_t)((b * 2048 + q_lo + 8) * 16 + h) * 64 + dv] =
            make_float2(acc[nt][2] * rs[1], acc[nt][3] * rs[1]);
    }
}

// ---------------------------------------------------------------------------
extern "C" void kernel_launch(void* const* d_in, const int* in_sizes, int n_in,
                              void* d_out, int out_size)
{
    const float* Q    = (const float*)d_in[0];
    const float* mask = (const float*)d_in[1];
    const float* Wq   = (const float*)d_in[2];
    const float* bq   = (const float*)d_in[3];
    const float* Wk   = (const float*)d_in[4];
    const float* bk   = (const float*)d_in[5];
    const float* Wv   = (const float*)d_in[6];
    const float* bv   = (const float*)d_in[7];
    float* out = (float*)d_out;

    cudaFuncSetAttribute(attn_kernel,
                         cudaFuncAttributeMaxDynamicSharedMemorySize, ATTN_SMEM_BYTES);

    round_kernel<<<dim3(4096, 4), 256>>>(Q, Wq, Wk, Wv);
    proj_kernel<<<dim3(8, 32, 3), 256>>>(bq, bk, bv);
    attn_kernel<<<dim3(16, 32), 256, ATTN_SMEM_BYTES>>>(mask, out);
}

// round 14
// speedup vs baseline: 1.2694x; 1.0303x over previous
#include <cuda_runtime.h>
#include <cuda_fp16.h>
#include <cstdint>

// Shapes: Q[2,2048,1024], mask[2,2048], W_*[1024,1024], b_*[1024], out[2,2048,1024] fp32
// Scratch (fp16): g_qh (pre-scaled by 0.125 — exact exponent shift), g_kh [bh][s][64];
//                 g_vTh [bh][64(dv)][2048(s)]; g_Ah = fp16 Q-input, g_Wh = fp16 weights
__device__ __align__(16) __half g_qh [2 * 16 * 2048 * 64];
__device__ __align__(16) __half g_kh [2 * 16 * 2048 * 64];
__device__ __align__(16) __half g_vTh[2 * 16 * 64 * 2048];
__device__ __align__(16) __half g_Ah [4096 * 1024];
__device__ __align__(16) __half g_Wh [3][1024 * 1024];

// ---------------------------------------------------------------------------
// helpers
// ---------------------------------------------------------------------------
__device__ __forceinline__ uint32_t packh(float lo, float hi) {
    uint32_t d;
    asm("cvt.rn.f16x2.f32 %0, %1, %2;" : "=r"(d) : "f"(hi), "f"(lo));
    return d;
}
__device__ __forceinline__ uint32_t smem_u32(const void* p) {
    uint32_t a;
    asm("{ .reg .u64 t; cvta.to.shared.u64 t, %1; cvt.u32.u64 %0, t; }" : "=r"(a) : "l"(p));
    return a;
}
__device__ __forceinline__ void ldsm4(uint32_t* r, uint32_t addr) {
    asm volatile("ldmatrix.sync.aligned.m8n8.x4.shared.b16 {%0,%1,%2,%3}, [%4];"
                 : "=r"(r[0]), "=r"(r[1]), "=r"(r[2]), "=r"(r[3]) : "r"(addr));
}
__device__ __forceinline__ void mma16(float* c, const uint32_t* a, const uint32_t* b) {
    asm volatile(
        "mma.sync.aligned.m16n8k16.row.col.f32.f16.f16.f32 "
        "{%0,%1,%2,%3}, {%4,%5,%6,%7}, {%8,%9}, {%0,%1,%2,%3};"
        : "+f"(c[0]), "+f"(c[1]), "+f"(c[2]), "+f"(c[3])
        : "r"(a[0]), "r"(a[1]), "r"(a[2]), "r"(a[3]), "r"(b[0]), "r"(b[1]));
}
__device__ __forceinline__ void cpa16(uint32_t dst, const void* src) {
    asm volatile("cp.async.cg.shared.global [%0], [%1], 16;" :: "r"(dst), "l"(src));
}
#define CP_COMMIT() asm volatile("cp.async.commit_group;" ::: "memory")
#define CP_WAIT1()  asm volatile("cp.async.wait_group 1;" ::: "memory")

// A-operand ldmatrix byte address (16-row x k16 tile)
__device__ __forceinline__ uint32_t a_addr_h(const __half* base, int rowBase, int stride, int lane) {
    const int row = rowBase + ((lane >> 3) & 1) * 8 + (lane & 7);
    const int col = (lane >> 4) << 3;
    return smem_u32(base + row * stride + col);
}
// B-pair ldmatrix byte address -> {r0,r1}=n-group0, {r2,r3}=n-group1
__device__ __forceinline__ uint32_t b_addr_h(const __half* base, int rowBase, int stride, int lane) {
    const int sel = lane >> 3;
    const int row = rowBase + (sel >> 1) * 8 + (lane & 7);
    const int col = (sel & 1) << 3;
    return smem_u32(base + row * stride + col);
}

// ---------------------------------------------------------------------------
// fp16 pre-convert
// ---------------------------------------------------------------------------
__global__ __launch_bounds__(256)
void round_kernel(const float* __restrict__ Qin,
                  const float* __restrict__ Wq,
                  const float* __restrict__ Wk,
                  const float* __restrict__ Wv)
{
    const int i = blockIdx.x * 256 + threadIdx.x;
    const int y = blockIdx.y;
    const float* src;
    __half* dst;
    if (y == 0) { src = Qin; dst = g_Ah; }
    else        { if (i >= 262144) return;
                  src = (y == 1) ? Wq : (y == 2) ? Wk : Wv; dst = g_Wh[y - 1]; }
    const float4 v = ((const float4*)src)[i];
    ((uint2*)dst)[i] = make_uint2(packh(v.x, v.y), packh(v.z, v.w));
}

// ---------------------------------------------------------------------------
// Projection GEMM (fp16 mma) — R12 structure: tile M=128 N=128, K-chunk 64,
// cp.async 2-stage. Q epilogue pre-scales by 0.125 (exact exponent shift).
// ---------------------------------------------------------------------------
#define PSTR 72
#define PSTG_B (256 * PSTR * 2)

__global__ __launch_bounds__(256, 2)
void proj_kernel(const float* __restrict__ bq,
                 const float* __restrict__ bk,
                 const float* __restrict__ bv)
{
    __shared__ __align__(16) __half sbuf[2][256 * PSTR];
    __shared__ float s_bias[128];

    const int proj = blockIdx.z;
    const __half* A = g_Ah;
    const __half* W = g_Wh[proj];
    const float* bias = (proj == 0) ? bq : (proj == 1) ? bk : bv;

    const int tid  = threadIdx.x;
    const int lane = tid & 31;
    const int w    = tid >> 5;
    const int g    = lane >> 2;
    const int cq   = lane & 3;
    const int mw   = (w & 3) << 5;
    const int nw   = (w >> 2) << 6;
    const int m0   = blockIdx.y << 7;
    const int n0   = blockIdx.x << 7;

    if (tid < 128) s_bias[tid] = bias[n0 + tid];

    const uint32_t uS = smem_u32(sbuf);

    const uint32_t aAdr0 = a_addr_h(&sbuf[0][0], mw,      PSTR, lane);
    const uint32_t aAdr1 = a_addr_h(&sbuf[0][0], mw + 16, PSTR, lane);
    uint32_t bAdr[4];
    #pragma unroll
    for (int j = 0; j < 4; j++)
        bAdr[j] = b_addr_h(&sbuf[0][128 * PSTR], nw + 16 * j, PSTR, lane);

    const __half* srcbase = (tid < 128) ? (A + (size_t)(m0 + tid) * 1024)
                                        : (W + (size_t)(n0 + tid - 128) * 1024);
    const uint32_t drow = uS + (uint32_t)(tid * PSTR) * 2;

    float acc[2][8][4] = {};

    #pragma unroll
    for (int st = 0; st < 2; st++) {
        const int k0 = st << 6;
        #pragma unroll
        for (int i = 0; i < 8; i++)
            cpa16(drow + st * PSTG_B + i * 16, srcbase + k0 + i * 8);
        CP_COMMIT();
    }

    for (int c = 0; c < 16; ++c) {
        const int st = c & 1;
        const uint32_t stoff = (uint32_t)st * PSTG_B;
        CP_WAIT1();
        __syncthreads();

        #pragma unroll
        for (int ks = 0; ks < 4; ++ks) {
            const uint32_t koff = stoff + (uint32_t)(ks << 5);
            uint32_t a0[4], a1[4];
            ldsm4(a0, aAdr0 + koff);
            ldsm4(a1, aAdr1 + koff);
            #pragma unroll
            for (int j = 0; j < 4; j++) {
                uint32_t bb[4];
                ldsm4(bb, bAdr[j] + koff);
                mma16(acc[0][2 * j],     a0, bb);
                mma16(acc[0][2 * j + 1], a0, bb + 2);
                mma16(acc[1][2 * j],     a1, bb);
                mma16(acc[1][2 * j + 1], a1, bb + 2);
            }
        }
        __syncthreads();

        if (c + 2 < 16) {
            const int k0 = (c + 2) << 6;
            #pragma unroll
            for (int i = 0; i < 8; i++)
                cpa16(drow + stoff + i * 16, srcbase + k0 + i * 8);
        }
        CP_COMMIT();
    }

    const int h = (n0 + nw) >> 6;
    const float qscale = (proj == 0) ? 0.125f : 1.0f;   // fold 1/sqrt(DK) into Q (exact)
    #pragma unroll
    for (int mt = 0; mt < 2; mt++) {
        const int m  = m0 + mw + (mt << 4) + g;
        const int b_ = m >> 11;
        const int s  = m & 2047;
        const int bh = b_ * 16 + h;
        #pragma unroll
        for (int nt = 0; nt < 8; nt++) {
            const int col  = nw + (nt << 3) + (cq << 1);
            const int colh = col & 63;
            const float b0 = s_bias[col], b1 = s_bias[col + 1];
            if (proj < 2) {
                __half* dst = (proj == 0) ? g_qh : g_kh;
                *(uint32_t*)&dst[(size_t)(bh * 2048 + s) * 64 + colh] =
                    packh((acc[mt][nt][0] + b0) * qscale, (acc[mt][nt][1] + b1) * qscale);
                *(uint32_t*)&dst[(size_t)(bh * 2048 + s + 8) * 64 + colh] =
                    packh((acc[mt][nt][2] + b0) * qscale, (acc[mt][nt][3] + b1) * qscale);
            } else {
                g_vTh[(size_t)(bh * 64 + colh)     * 2048 + s]     = __float2half_rn(acc[mt][nt][0] + b0);
                g_vTh[(size_t)(bh * 64 + colh + 1) * 2048 + s]     = __float2half_rn(acc[mt][nt][1] + b1);
                g_vTh[(size_t)(bh * 64 + colh)     * 2048 + s + 8] = __float2half_rn(acc[mt][nt][2] + b0);
                g_vTh[(size_t)(bh * 64 + colh + 1) * 2048 + s + 8] = __float2half_rn(acc[mt][nt][3] + b1);
            }
        }
    }
}

// ---------------------------------------------------------------------------
// Attention v11 (fp16): 256 thr, warp = 16q x 64 keys (R13 layout), but with a
// 3-stage cp.async ring and ONE barrier per kt (CUTLASS multistage pattern).
// Q pre-scaled by 0.125 in proj -> exp input bit-identical, no per-element mul.
// ---------------------------------------------------------------------------
#define HSTR 72
#define KSTG_B (64 * HSTR * 2)
#define ATTN_SMEM_BYTES (128 * HSTR * 2 + 6 * KSTG_B + 3 * 64 * 4)

__global__ __launch_bounds__(256, 2)
void attn_kernel(const float* __restrict__ mask, float* __restrict__ out)
{
    extern __shared__ __align__(16) __half smh[];
    __half* Qs = smh;                        // [128 q][72]
    __half* Ks = smh + 128 * HSTR;           // [3][64 key][72]
    __half* Vs = Ks + 3 * 64 * HSTR;         // [3][64 dv][72]
    float* maskS = (float*)(Vs + 3 * 64 * HSTR);   // [3][64]

    const int tid  = threadIdx.x;
    const int lane = tid & 31;
    const int w    = tid >> 5;               // 0..7
    const int g    = lane >> 2;
    const int cq   = lane & 3;
    const int qw   = w << 4;                 // warp q offset (0..112)
    const int q0   = blockIdx.x << 7;
    const int bh   = blockIdx.y;
    const int b    = bh >> 4;
    const int h    = bh & 15;

    const uint32_t uQ = smem_u32(Qs);
    const uint32_t uK = smem_u32(Ks);
    const uint32_t uV = smem_u32(Vs);
    const uint32_t uM = smem_u32(maskS);

    uint32_t kAdr[4], vAdr[4];
    #pragma unroll
    for (int j = 0; j < 4; j++) {
        kAdr[j] = b_addr_h(Ks, 16 * j, HSTR, lane);
        vAdr[j] = b_addr_h(Vs, 16 * j, HSTR, lane);
    }

    // loaders (256 threads): Q: (row, 64B half); K/V: (row, 32B quarter)
    const int qrow = tid >> 1;
    const int qB   = (tid & 1) * 64;
    const int kvrow = tid >> 2;
    const int kvB   = (tid & 3) * 32;

    // ---- prologue: Q + tile0 -> group0 ; tile1 -> group1 ----
    #pragma unroll
    for (int i = 0; i < 4; i++)
        cpa16(uQ + (uint32_t)(qrow * HSTR) * 2 + qB + i * 16,
              g_qh + (size_t)(bh * 2048 + q0 + qrow) * 64 + (qB >> 1) + i * 8);
    #pragma unroll
    for (int st = 0; st < 2; st++) {
        const int kb = st << 6;
        #pragma unroll
        for (int i = 0; i < 2; i++) {
            cpa16(uK + st * KSTG_B + (uint32_t)(kvrow * HSTR) * 2 + kvB + i * 16,
                  g_kh + (size_t)(bh * 2048 + kb + kvrow) * 64 + (kvB >> 1) + i * 8);
            cpa16(uV + st * KSTG_B + (uint32_t)(kvrow * HSTR) * 2 + kvB + i * 16,
                  g_vTh + (size_t)(bh * 64 + kvrow) * 2048 + kb + (kvB >> 1) + i * 8);
        }
        if (tid < 16) cpa16(uM + st * 256 + tid * 16, mask + b * 2048 + kb + tid * 4);
        CP_COMMIT();
    }
    CP_WAIT1();
    __syncthreads();

    // ---- Q fragments: load once, keep in regs ----
    uint32_t qa[4][4];
    {
        const uint32_t qb = a_addr_h(Qs, qw, HSTR, lane);
        #pragma unroll
        for (int ks = 0; ks < 4; ks++)
            ldsm4(qa[ks], qb + (ks << 5));
    }

    float acc[8][4] = {};
    float rs[2] = {};

    int cur = 0;
    for (int kt = 0; kt < 32; kt++) {
        const uint32_t stoff = (uint32_t)cur * KSTG_B;
        CP_WAIT1();           // tile kt complete (<=1 newer group pending)
        __syncthreads();      // visibility + stage-(kt-1) consumption complete

        // ---- S = Q K^T : 4 k16 steps over dk ----
        float s[8][4] = {};
        #pragma unroll
        for (int ks = 0; ks < 4; ks++) {
            const uint32_t koff = stoff + (uint32_t)(ks << 5);
            #pragma unroll
            for (int j = 0; j < 4; j++) {
                uint32_t bb[4];
                ldsm4(bb, kAdr[j] + koff);
                mma16(s[2 * j],     qa[ks], bb);
                mma16(s[2 * j + 1], qa[ks], bb + 2);
            }
        }

        // ---- P = exp(S)*mask (scale pre-folded into Q); unrounded row sums ----
        #pragma unroll
        for (int nt = 0; nt < 8; nt++) {
            const float2 mm = *(const float2*)&maskS[cur * 64 + (nt << 3) + (cq << 1)];
            const float p00 = __expf(s[nt][0]) * mm.x;
            const float p01 = __expf(s[nt][1]) * mm.y;
            const float p10 = __expf(s[nt][2]) * mm.x;
            const float p11 = __expf(s[nt][3]) * mm.y;
            rs[0] += p00 + p01;
            rs[1] += p10 + p11;
            s[nt][0] = p00; s[nt][1] = p01; s[nt][2] = p10; s[nt][3] = p11;
        }

        // ---- acc += P @ V ----
        #pragma unroll
        for (int t = 0; t < 4; t++) {
            const uint32_t koff = stoff + (uint32_t)(t << 5);
            uint32_t a[4] = { packh(s[2*t][0],   s[2*t][1]),   packh(s[2*t][2],   s[2*t][3]),
                              packh(s[2*t+1][0], s[2*t+1][1]), packh(s[2*t+1][2], s[2*t+1][3]) };
            #pragma unroll
            for (int j = 0; j < 4; j++) {
                uint32_t bb[4];
                ldsm4(bb, vAdr[j] + koff);
                mma16(acc[2 * j],     a, bb);
                mma16(acc[2 * j + 1], a, bb + 2);
            }
        }

        // ---- refill stage (cur+2)%3 with tile kt+2 (that stage was consumed
        //      at iter kt-1; every warp passed this iteration's barrier) ----
        if (kt + 2 < 32) {
            int rf = cur + 2; if (rf >= 3) rf -= 3;
            const uint32_t rfoff = (uint32_t)rf * KSTG_B;
            const int kn = (kt + 2) << 6;
            #pragma unroll
            for (int i = 0; i < 2; i++) {
                cpa16(uK + rfoff + (uint32_t)(kvrow * HSTR) * 2 + kvB + i * 16,
                      g_kh + (size_t)(bh * 2048 + kn + kvrow) * 64 + (kvB >> 1) + i * 8);
                cpa16(uV + rfoff + (uint32_t)(kvrow * HSTR) * 2 + kvB + i * 16,
                      g_vTh + (size_t)(bh * 64 + kvrow) * 2048 + kn + (kvB >> 1) + i * 8);
            }
            if (tid < 16) cpa16(uM + rf * 256 + tid * 16, mask + b * 2048 + kn + tid * 4);
        }
        CP_COMMIT();
        cur = (cur + 1 == 3) ? 0 : cur + 1;
    }

    // ---- denominator: reduce across the 4 cq lanes ----
    #pragma unroll
    for (int i = 0; i < 2; i++) {
        rs[i] += __shfl_xor_sync(0xffffffffu, rs[i], 1);
        rs[i] += __shfl_xor_sync(0xffffffffu, rs[i], 2);
        rs[i] = 1.0f / (rs[i] + 1e-8f);
    }

    const int q_lo = q0 + qw + g;
    #pragma unroll
    for (int nt = 0; nt < 8; nt++) {
        const int dv = (nt << 3) + (cq << 1);
        *(float2*)&out[(size_t)((b * 2048 + q_lo) * 16 + h) * 64 + dv] =
            make_float2(acc[nt][0] * rs[0], acc[nt][1] * rs[0]);
        *(float2*)&out[(size_t)((b * 2048 + q_lo + 8) * 16 + h) * 64 + dv] =
            make_float2(acc[nt][2] * rs[1], acc[nt][3] * rs[1]);
    }
}

// ---------------------------------------------------------------------------
extern "C" void kernel_launch(void* const* d_in, const int* in_sizes, int n_in,
                              void* d_out, int out_size)
{
    const float* Q    = (const float*)d_in[0];
    const float* mask = (const float*)d_in[1];
    const float* Wq   = (const float*)d_in[2];
    const float* bq   = (const float*)d_in[3];
    const float* Wk   = (const float*)d_in[4];
    const float* bk   = (const float*)d_in[5];
    const float* Wv   = (const float*)d_in[6];
    const float* bv   = (const float*)d_in[7];
    float* out = (float*)d_out;

    cudaFuncSetAttribute(attn_kernel,
                         cudaFuncAttributeMaxDynamicSharedMemorySize, ATTN_SMEM_BYTES);

    round_kernel<<<dim3(4096, 4), 256>>>(Q, Wq, Wk, Wv);
    proj_kernel<<<dim3(8, 32, 3), 256>>>(bq, bk, bv);
    attn_kernel<<<dim3(16, 32), 256, ATTN_SMEM_BYTES>>>(mask, out);
}

// round 15
// speedup vs baseline: 1.2803x; 1.0086x over previous
#include <cuda_runtime.h>
#include <cuda_fp16.h>
#include <cstdint>

// Shapes: Q[2,2048,1024], mask[2,2048], W_*[1024,1024], b_*[1024], out[2,2048,1024] fp32
// Scratch (fp16): g_qh (pre-scaled by 0.125), g_kh [bh][s][64];
//                 g_vTh [bh][64(dv)][2048(s)]; g_Ah = fp16 Q-input, g_Wh = fp16 weights
__device__ __align__(16) __half g_qh [2 * 16 * 2048 * 64];
__device__ __align__(16) __half g_kh [2 * 16 * 2048 * 64];
__device__ __align__(16) __half g_vTh[2 * 16 * 64 * 2048];
__device__ __align__(16) __half g_Ah [4096 * 1024];
__device__ __align__(16) __half g_Wh [3][1024 * 1024];

// ---------------------------------------------------------------------------
// helpers
// ---------------------------------------------------------------------------
__device__ __forceinline__ uint32_t packh(float lo, float hi) {
    uint32_t d;
    asm("cvt.rn.f16x2.f32 %0, %1, %2;" : "=r"(d) : "f"(hi), "f"(lo));
    return d;
}
__device__ __forceinline__ uint32_t smem_u32(const void* p) {
    uint32_t a;
    asm("{ .reg .u64 t; cvta.to.shared.u64 t, %1; cvt.u32.u64 %0, t; }" : "=r"(a) : "l"(p));
    return a;
}
__device__ __forceinline__ void ldsm4(uint32_t* r, uint32_t addr) {
    asm volatile("ldmatrix.sync.aligned.m8n8.x4.shared.b16 {%0,%1,%2,%3}, [%4];"
                 : "=r"(r[0]), "=r"(r[1]), "=r"(r[2]), "=r"(r[3]) : "r"(addr));
}
__device__ __forceinline__ void mma16(float* c, const uint32_t* a, const uint32_t* b) {
    asm volatile(
        "mma.sync.aligned.m16n8k16.row.col.f32.f16.f16.f32 "
        "{%0,%1,%2,%3}, {%4,%5,%6,%7}, {%8,%9}, {%0,%1,%2,%3};"
        : "+f"(c[0]), "+f"(c[1]), "+f"(c[2]), "+f"(c[3])
        : "r"(a[0]), "r"(a[1]), "r"(a[2]), "r"(a[3]), "r"(b[0]), "r"(b[1]));
}
__device__ __forceinline__ void cpa16(uint32_t dst, const void* src) {
    asm volatile("cp.async.cg.shared.global [%0], [%1], 16;" :: "r"(dst), "l"(src));
}
#define CP_COMMIT() asm volatile("cp.async.commit_group;" ::: "memory")
#define CP_WAIT1()  asm volatile("cp.async.wait_group 1;" ::: "memory")
#define CP_WAIT2()  asm volatile("cp.async.wait_group 2;" ::: "memory")

// A-operand ldmatrix byte address (16-row x k16 tile)
__device__ __forceinline__ uint32_t a_addr_h(const __half* base, int rowBase, int stride, int lane) {
    const int row = rowBase + ((lane >> 3) & 1) * 8 + (lane & 7);
    const int col = (lane >> 4) << 3;
    return smem_u32(base + row * stride + col);
}
// B-pair ldmatrix byte address -> {r0,r1}=n-group0, {r2,r3}=n-group1
__device__ __forceinline__ uint32_t b_addr_h(const __half* base, int rowBase, int stride, int lane) {
    const int sel = lane >> 3;
    const int row = rowBase + (sel >> 1) * 8 + (lane & 7);
    const int col = (sel & 1) << 3;
    return smem_u32(base + row * stride + col);
}

// ---------------------------------------------------------------------------
// fp16 pre-convert
// ---------------------------------------------------------------------------
__global__ __launch_bounds__(256)
void round_kernel(const float* __restrict__ Qin,
                  const float* __restrict__ Wq,
                  const float* __restrict__ Wk,
                  const float* __restrict__ Wv)
{
    const int i = blockIdx.x * 256 + threadIdx.x;
    const int y = blockIdx.y;
    const float* src;
    __half* dst;
    if (y == 0) { src = Qin; dst = g_Ah; }
    else        { if (i >= 262144) return;
                  src = (y == 1) ? Wq : (y == 2) ? Wk : Wv; dst = g_Wh[y - 1]; }
    const float4 v = ((const float4*)src)[i];
    ((uint2*)dst)[i] = make_uint2(packh(v.x, v.y), packh(v.z, v.w));
}

// ---------------------------------------------------------------------------
// Projection GEMM (fp16 mma): tile M=128 N=128, K-chunk 64, 3-stage cp.async
// ring, ONE barrier per iteration. Dynamic smem (110.6 KB). grid = (8, 32, 3).
// ---------------------------------------------------------------------------
#define PSTR 72
#define PSTG_B (256 * PSTR * 2)        // 36864 bytes per stage
#define PROJ_SMEM_BYTES (3 * PSTG_B)

__global__ __launch_bounds__(256, 2)
void proj_kernel(const float* __restrict__ bq,
                 const float* __restrict__ bk,
                 const float* __restrict__ bv)
{
    extern __shared__ __align__(16) __half psm[];
    __shared__ float s_bias[128];

    const int proj = blockIdx.z;
    const __half* A = g_Ah;
    const __half* W = g_Wh[proj];
    const float* bias = (proj == 0) ? bq : (proj == 1) ? bk : bv;

    const int tid  = threadIdx.x;
    const int lane = tid & 31;
    const int w    = tid >> 5;
    const int g    = lane >> 2;
    const int cq   = lane & 3;
    const int mw   = (w & 3) << 5;
    const int nw   = (w >> 2) << 6;
    const int m0   = blockIdx.y << 7;
    const int n0   = blockIdx.x << 7;

    if (tid < 128) s_bias[tid] = bias[n0 + tid];

    const uint32_t uS = smem_u32(psm);

    const uint32_t aAdr0 = a_addr_h(psm, mw,      PSTR, lane);
    const uint32_t aAdr1 = a_addr_h(psm, mw + 16, PSTR, lane);
    uint32_t bAdr[4];
    #pragma unroll
    for (int j = 0; j < 4; j++)
        bAdr[j] = b_addr_h(psm + 128 * PSTR, nw + 16 * j, PSTR, lane);

    const __half* srcbase = (tid < 128) ? (A + (size_t)(m0 + tid) * 1024)
                                        : (W + (size_t)(n0 + tid - 128) * 1024);
    const uint32_t drow = uS + (uint32_t)(tid * PSTR) * 2;

    float acc[2][8][4] = {};

    // prologue: chunks 0,1 -> stages 0,1
    #pragma unroll
    for (int st = 0; st < 2; st++) {
        const int k0 = st << 6;
        #pragma unroll
        for (int i = 0; i < 8; i++)
            cpa16(drow + st * PSTG_B + i * 16, srcbase + k0 + i * 8);
        CP_COMMIT();
    }

    int cur = 0;
    for (int c = 0; c < 16; ++c) {
        const uint32_t stoff = (uint32_t)cur * PSTG_B;
        CP_WAIT1();
        __syncthreads();

        #pragma unroll
        for (int ks = 0; ks < 4; ++ks) {
            const uint32_t koff = stoff + (uint32_t)(ks << 5);
            uint32_t a0[4], a1[4];
            ldsm4(a0, aAdr0 + koff);
            ldsm4(a1, aAdr1 + koff);
            #pragma unroll
            for (int j = 0; j < 4; j++) {
                uint32_t bb[4];
                ldsm4(bb, bAdr[j] + koff);
                mma16(acc[0][2 * j],     a0, bb);
                mma16(acc[0][2 * j + 1], a0, bb + 2);
                mma16(acc[1][2 * j],     a1, bb);
                mma16(acc[1][2 * j + 1], a1, bb + 2);
            }
        }

        // refill stage (cur+2)%3 with chunk c+2 (consumed at iter c-1; all
        // warps passed this iteration's barrier)
        if (c + 2 < 16) {
            int rf = cur + 2; if (rf >= 3) rf -= 3;
            const uint32_t rfoff = (uint32_t)rf * PSTG_B;
            const int k0 = (c + 2) << 6;
            #pragma unroll
            for (int i = 0; i < 8; i++)
                cpa16(drow + rfoff + i * 16, srcbase + k0 + i * 8);
        }
        CP_COMMIT();
        cur = (cur + 1 == 3) ? 0 : cur + 1;
    }

    const int h = (n0 + nw) >> 6;
    const float qscale = (proj == 0) ? 0.125f : 1.0f;
    #pragma unroll
    for (int mt = 0; mt < 2; mt++) {
        const int m  = m0 + mw + (mt << 4) + g;
        const int b_ = m >> 11;
        const int s  = m & 2047;
        const int bh = b_ * 16 + h;
        #pragma unroll
        for (int nt = 0; nt < 8; nt++) {
            const int col  = nw + (nt << 3) + (cq << 1);
            const int colh = col & 63;
            const float b0 = s_bias[col], b1 = s_bias[col + 1];
            if (proj < 2) {
                __half* dst = (proj == 0) ? g_qh : g_kh;
                *(uint32_t*)&dst[(size_t)(bh * 2048 + s) * 64 + colh] =
                    packh((acc[mt][nt][0] + b0) * qscale, (acc[mt][nt][1] + b1) * qscale);
                *(uint32_t*)&dst[(size_t)(bh * 2048 + s + 8) * 64 + colh] =
                    packh((acc[mt][nt][2] + b0) * qscale, (acc[mt][nt][3] + b1) * qscale);
            } else {
                g_vTh[(size_t)(bh * 64 + colh)     * 2048 + s]     = __float2half_rn(acc[mt][nt][0] + b0);
                g_vTh[(size_t)(bh * 64 + colh + 1) * 2048 + s]     = __float2half_rn(acc[mt][nt][1] + b1);
                g_vTh[(size_t)(bh * 64 + colh)     * 2048 + s + 8] = __float2half_rn(acc[mt][nt][2] + b0);
                g_vTh[(size_t)(bh * 64 + colh + 1) * 2048 + s + 8] = __float2half_rn(acc[mt][nt][3] + b1);
            }
        }
    }
}

// ---------------------------------------------------------------------------
// Attention v12 (fp16): 256 thr, warp = 16q x 64 keys, 4-stage cp.async ring
// with wait_group 2 (two iterations of load slack), ONE barrier per kt.
// ---------------------------------------------------------------------------
#define HSTR 72
#define KSTG_B (64 * HSTR * 2)
#define ATTN_SMEM_BYTES (128 * HSTR * 2 + 8 * KSTG_B + 4 * 64 * 4)

__global__ __launch_bounds__(256, 2)
void attn_kernel(const float* __restrict__ mask, float* __restrict__ out)
{
    extern __shared__ __align__(16) __half smh[];
    __half* Qs = smh;                        // [128 q][72]
    __half* Ks = smh + 128 * HSTR;           // [4][64 key][72]
    __half* Vs = Ks + 4 * 64 * HSTR;         // [4][64 dv][72]
    float* maskS = (float*)(Vs + 4 * 64 * HSTR);   // [4][64]

    const int tid  = threadIdx.x;
    const int lane = tid & 31;
    const int w    = tid >> 5;
    const int g    = lane >> 2;
    const int cq   = lane & 3;
    const int qw   = w << 4;
    const int q0   = blockIdx.x << 7;
    const int bh   = blockIdx.y;
    const int b    = bh >> 4;
    const int h    = bh & 15;

    const uint32_t uQ = smem_u32(Qs);
    const uint32_t uK = smem_u32(Ks);
    const uint32_t uV = smem_u32(Vs);
    const uint32_t uM = smem_u32(maskS);

    uint32_t kAdr[4], vAdr[4];
    #pragma unroll
    for (int j = 0; j < 4; j++) {
        kAdr[j] = b_addr_h(Ks, 16 * j, HSTR, lane);
        vAdr[j] = b_addr_h(Vs, 16 * j, HSTR, lane);
    }

    const int qrow = tid >> 1;
    const int qB   = (tid & 1) * 64;
    const int kvrow = tid >> 2;
    const int kvB   = (tid & 3) * 32;

    // ---- prologue: Q + tiles 0,1,2 -> stages 0,1,2 (3 commits) ----
    #pragma unroll
    for (int i = 0; i < 4; i++)
        cpa16(uQ + (uint32_t)(qrow * HSTR) * 2 + qB + i * 16,
              g_qh + (size_t)(bh * 2048 + q0 + qrow) * 64 + (qB >> 1) + i * 8);
    #pragma unroll
    for (int st = 0; st < 3; st++) {
        const int kb = st << 6;
        #pragma unroll
        for (int i = 0; i < 2; i++) {
            cpa16(uK + st * KSTG_B + (uint32_t)(kvrow * HSTR) * 2 + kvB + i * 16,
                  g_kh + (size_t)(bh * 2048 + kb + kvrow) * 64 + (kvB >> 1) + i * 8);
            cpa16(uV + st * KSTG_B + (uint32_t)(kvrow * HSTR) * 2 + kvB + i * 16,
                  g_vTh + (size_t)(bh * 64 + kvrow) * 2048 + kb + (kvB >> 1) + i * 8);
        }
        if (tid < 16) cpa16(uM + st * 256 + tid * 16, mask + b * 2048 + kb + tid * 4);
        CP_COMMIT();
    }
    CP_WAIT2();           // tile 0 (+Q) complete
    __syncthreads();

    // ---- Q fragments: load once, keep in regs ----
    uint32_t qa[4][4];
    {
        const uint32_t qb = a_addr_h(Qs, qw, HSTR, lane);
        #pragma unroll
        for (int ks = 0; ks < 4; ks++)
            ldsm4(qa[ks], qb + (ks << 5));
    }

    float acc[8][4] = {};
    float rs[2] = {};

    int cur = 0;
    for (int kt = 0; kt < 32; kt++) {
        const uint32_t stoff = (uint32_t)cur * KSTG_B;
        CP_WAIT2();       // tile kt complete (<=2 newer groups pending)
        __syncthreads();  // visibility + stage-(kt-1) consumption complete

        // ---- S = Q K^T ----
        float s[8][4] = {};
        #pragma unroll
        for (int ks = 0; ks < 4; ks++) {
            const uint32_t koff = stoff + (uint32_t)(ks << 5);
            #pragma unroll
            for (int j = 0; j < 4; j++) {
                uint32_t bb[4];
                ldsm4(bb, kAdr[j] + koff);
                mma16(s[2 * j],     qa[ks], bb);
                mma16(s[2 * j + 1], qa[ks], bb + 2);
            }
        }

        // ---- P = exp(S)*mask; unrounded row sums ----
        #pragma unroll
        for (int nt = 0; nt < 8; nt++) {
            const float2 mm = *(const float2*)&maskS[cur * 64 + (nt << 3) + (cq << 1)];
            const float p00 = __expf(s[nt][0]) * mm.x;
            const float p01 = __expf(s[nt][1]) * mm.y;
            const float p10 = __expf(s[nt][2]) * mm.x;
            const float p11 = __expf(s[nt][3]) * mm.y;
            rs[0] += p00 + p01;
            rs[1] += p10 + p11;
            s[nt][0] = p00; s[nt][1] = p01; s[nt][2] = p10; s[nt][3] = p11;
        }

        // ---- acc += P @ V ----
        #pragma unroll
        for (int t = 0; t < 4; t++) {
            const uint32_t koff = stoff + (uint32_t)(t << 5);
            uint32_t a[4] = { packh(s[2*t][0],   s[2*t][1]),   packh(s[2*t][2],   s[2*t][3]),
                              packh(s[2*t+1][0], s[2*t+1][1]), packh(s[2*t+1][2], s[2*t+1][3]) };
            #pragma unroll
            for (int j = 0; j < 4; j++) {
                uint32_t bb[4];
                ldsm4(bb, vAdr[j] + koff);
                mma16(acc[2 * j],     a, bb);
                mma16(acc[2 * j + 1], a, bb + 2);
            }
        }

        // ---- refill stage (cur+3)%4 with tile kt+3 (consumed at iter kt-1) ----
        if (kt + 3 < 32) {
            int rf = cur + 3; if (rf >= 4) rf -= 4;
            const uint32_t rfoff = (uint32_t)rf * KSTG_B;
            const int kn = (kt + 3) << 6;
            #pragma unroll
            for (int i = 0; i < 2; i++) {
                cpa16(uK + rfoff + (uint32_t)(kvrow * HSTR) * 2 + kvB + i * 16,
                      g_kh + (size_t)(bh * 2048 + kn + kvrow) * 64 + (kvB >> 1) + i * 8);
                cpa16(uV + rfoff + (uint32_t)(kvrow * HSTR) * 2 + kvB + i * 16,
                      g_vTh + (size_t)(bh * 64 + kvrow) * 2048 + kn + (kvB >> 1) + i * 8);
            }
            if (tid < 16) cpa16(uM + rf * 256 + tid * 16, mask + b * 2048 + kn + tid * 4);
        }
        CP_COMMIT();
        cur = (cur + 1 == 4) ? 0 : cur + 1;
    }

    // ---- denominator: reduce across the 4 cq lanes ----
    #pragma unroll
    for (int i = 0; i < 2; i++) {
        rs[i] += __shfl_xor_sync(0xffffffffu, rs[i], 1);
        rs[i] += __shfl_xor_sync(0xffffffffu, rs[i], 2);
        rs[i] = 1.0f / (rs[i] + 1e-8f);
    }

    const int q_lo = q0 + qw + g;
    #pragma unroll
    for (int nt = 0; nt < 8; nt++) {
        const int dv = (nt << 3) + (cq << 1);
        *(float2*)&out[(size_t)((b * 2048 + q_lo) * 16 + h) * 64 + dv] =
            make_float2(acc[nt][0] * rs[0], acc[nt][1] * rs[0]);
        *(float2*)&out[(size_t)((b * 2048 + q_lo + 8) * 16 + h) * 64 + dv] =
            make_float2(acc[nt][2] * rs[1], acc[nt][3] * rs[1]);
    }
}

// ---------------------------------------------------------------------------
extern "C" void kernel_launch(void* const* d_in, const int* in_sizes, int n_in,
                              void* d_out, int out_size)
{
    const float* Q    = (const float*)d_in[0];
    const float* mask = (const float*)d_in[1];
    const float* Wq   = (const float*)d_in[2];
    const float* bq   = (const float*)d_in[3];
    const float* Wk   = (const float*)d_in[4];
    const float* bk   = (const float*)d_in[5];
    const float* Wv   = (const float*)d_in[6];
    const float* bv   = (const float*)d_in[7];
    float* out = (float*)d_out;

    cudaFuncSetAttribute(proj_kernel,
                         cudaFuncAttributeMaxDynamicSharedMemorySize, PROJ_SMEM_BYTES);
    cudaFuncSetAttribute(attn_kernel,
                         cudaFuncAttributeMaxDynamicSharedMemorySize, ATTN_SMEM_BYTES);

    round_kernel<<<dim3(4096, 4), 256>>>(Q, Wq, Wk, Wv);
    proj_kernel<<<dim3(8, 32, 3), 256, PROJ_SMEM_BYTES>>>(bq, bk, bv);
    attn_kernel<<<dim3(16, 32), 256, ATTN_SMEM_BYTES>>>(mask, out);
}